// round 1
// baseline (speedup 1.0000x reference)
#include <cuda_runtime.h>
#include <math.h>

// Problem constants
constexpr int NB = 8;     // batch
constexpr int NQ = 512;   // query len
constexpr int NM = 512;   // memory len
constexpr int NR = 1024;  // reference len = NQ + NM
constexpr int NH = 16;    // heads
constexpr int NS = 64;    // size per head
constexpr int ND = 1024;  // hidden

// Scratch (device globals; no runtime allocation allowed)
__device__ float g_QC[(size_t)NB * NH * NQ * NS];   // (q+content_bias) proj, [b,h,q,s]
__device__ float g_QP[(size_t)NB * NH * NQ * NS];   // (q+position_bias) proj, [b,h,q,s]
__device__ float g_KC[(size_t)NB * NH * NR * NS];   // key-content, [b,h,r,s]
__device__ float g_V [(size_t)NB * NH * NR * NS];   // value, [b,h,r,s]
__device__ float g_KP[(size_t)NH * NR * NS];        // key-position, [h,k,s]
__device__ float g_CT[(size_t)NB * NH * NQ * NR];   // content logits -> probs (in-place)
__device__ float g_PP[(size_t)NB * NH * NQ * NR];   // positional logits (pre-shift index k)
__device__ float g_O [(size_t)NB * NQ * NH * NS];   // attn output, [b,q,h,s]

enum { MODE_Q = 0, MODE_KC = 1, MODE_V = 2, MODE_KP = 3, MODE_OUT = 4 };

// ---------------------------------------------------------------------------
// Generic NN SGEMM: C[n, c] = sum_k X[n, k] * W[k, c],  K = ND = 1024, C-cols = 1024.
// 128x128 block tile, BK=8, 256 threads, 8x8 microtile.
// Mode-specific input row gather + output scatter epilogues.
// ---------------------------------------------------------------------------
template <int MODE>
__global__ __launch_bounds__(256, 2)
void gemm_nn(const float* __restrict__ Xq, const float* __restrict__ Xm,
             const float* __restrict__ W,
             const float* __restrict__ cb, const float* __restrict__ pb,
             float* __restrict__ outp)
{
    __shared__ float As[8][128];   // [k][m] (transposed)
    __shared__ float Bs[8][128];   // [k][n]

    const int t  = threadIdx.x;
    const int m0 = blockIdx.y * 128;
    const int n0 = blockIdx.x * 128;
    const int tr = t >> 4;          // 0..15
    const int tc = t & 15;          // 0..15

    // A load mapping: each thread one float4 per chunk
    const int ar = t >> 1;          // 0..127 (row within tile)
    const int ak = (t & 1) * 4;     // 0 or 4
    // B load mapping
    const int bk = t >> 5;          // 0..7
    const int bn = (t & 31) * 4;    // 0..124

    // Resolve source row pointer
    const int grow = m0 + ar;
    const float* xrow;
    if (MODE == MODE_KC || MODE == MODE_V) {
        const int b = grow >> 10, r = grow & 1023;
        xrow = (r < NM) ? (Xm + (size_t)(b * NM + r) * ND)
                        : (Xq + (size_t)(b * NQ + (r - NM)) * ND);
    } else if (MODE == MODE_OUT) {
        xrow = g_O + (size_t)grow * ND;
    } else {
        xrow = Xq + (size_t)grow * ND;
    }

    float acc[8][8];
    #pragma unroll
    for (int a = 0; a < 8; a++)
        #pragma unroll
        for (int b2 = 0; b2 < 8; b2++) acc[a][b2] = 0.f;

    for (int k0 = 0; k0 < ND; k0 += 8) {
        float4 av = *(const float4*)(xrow + k0 + ak);
        float4 bv = *(const float4*)(W + (size_t)(k0 + bk) * ND + n0 + bn);
        As[ak + 0][ar] = av.x;
        As[ak + 1][ar] = av.y;
        As[ak + 2][ar] = av.z;
        As[ak + 3][ar] = av.w;
        *(float4*)&Bs[bk][bn] = bv;
        __syncthreads();

        #pragma unroll
        for (int kk = 0; kk < 8; kk++) {
            float a0[8], b0[8];
            *(float4*)&a0[0] = *(const float4*)&As[kk][tr * 8];
            *(float4*)&a0[4] = *(const float4*)&As[kk][tr * 8 + 4];
            *(float4*)&b0[0] = *(const float4*)&Bs[kk][tc * 8];
            *(float4*)&b0[4] = *(const float4*)&Bs[kk][tc * 8 + 4];
            #pragma unroll
            for (int a = 0; a < 8; a++)
                #pragma unroll
                for (int b2 = 0; b2 < 8; b2++)
                    acc[a][b2] += a0[a] * b0[b2];
        }
        __syncthreads();
    }

    // Epilogue: scatter per mode
    #pragma unroll
    for (int a = 0; a < 8; a++) {
        const int n = m0 + tr * 8 + a;
        #pragma unroll
        for (int b2 = 0; b2 < 8; b2++) {
            const int c = n0 + tc * 8 + b2;
            const float v = acc[a][b2];
            if (MODE == MODE_Q) {
                const int bb = n >> 9, q = n & 511;
                const int h = c >> 6, s = c & 63;
                const size_t o = (((size_t)(bb * NH + h)) * NQ + q) * NS + s;
                g_QC[o] = v + cb[c];
                g_QP[o] = v + pb[c];
            } else if (MODE == MODE_KC) {
                const int bb = n >> 10, r = n & 1023;
                const int h = c >> 6, s = c & 63;
                g_KC[(((size_t)(bb * NH + h)) * NR + r) * NS + s] = v;
            } else if (MODE == MODE_V) {
                const int bb = n >> 10, r = n & 1023;
                const int h = c >> 6, s = c & 63;
                g_V[(((size_t)(bb * NH + h)) * NR + r) * NS + s] = v;
            } else if (MODE == MODE_KP) {
                const int h = c >> 6, s = c & 63;
                g_KP[((size_t)h * NR + n) * NS + s] = v;
            } else { // MODE_OUT
                outp[(size_t)n * ND + c] = v;
            }
        }
    }
}

// ---------------------------------------------------------------------------
// Score GEMM (NT): C[i, j] = sum_s A[i, s] * B[j, s], K = 64 fully in smem.
// 64x64 tile, 256 threads, 4x4 microtile, batched over z = b*NH + h.
// PPMODE=0: content logits (QC x KC^T), causal tile skip.
// PPMODE=1: positional logits (QP x KP^T, KP shared across batch), band skip.
// ---------------------------------------------------------------------------
template <int PPMODE>
__global__ __launch_bounds__(256)
void score_gemm()
{
    const int z  = blockIdx.z;
    const int q0 = blockIdx.y * 64;
    const int r0 = blockIdx.x * 64;

    if (PPMODE == 0) {
        if (r0 >= q0 + 576) return;        // entire tile masked (r > q+512)
    } else {
        if (r0 + 63 < 448 - q0) return;    // entire tile below needed band (k < 511-q)
    }

    __shared__ float AsT[64][68];  // [s][i]
    __shared__ float BsT[64][68];  // [s][j]

    const int t = threadIdx.x;
    const float* A = (PPMODE ? g_QP : g_QC) + (size_t)z * NQ * NS + (size_t)q0 * NS;
    const float* B = PPMODE ? (g_KP + (size_t)(z & (NH - 1)) * NR * NS + (size_t)r0 * NS)
                            : (g_KC + (size_t)z * NR * NS + (size_t)r0 * NS);
    float* C = (PPMODE ? g_PP : g_CT) + (size_t)z * NQ * NR;

    const int row = t >> 2;  // 0..63
    #pragma unroll
    for (int p = 0; p < 4; p++) {
        const int cs = ((t & 3) + p * 4) * 4;  // 0..60
        float4 av = *(const float4*)(A + (size_t)row * NS + cs);
        float4 bv = *(const float4*)(B + (size_t)row * NS + cs);
        AsT[cs + 0][row] = av.x; AsT[cs + 1][row] = av.y;
        AsT[cs + 2][row] = av.z; AsT[cs + 3][row] = av.w;
        BsT[cs + 0][row] = bv.x; BsT[cs + 1][row] = bv.y;
        BsT[cs + 2][row] = bv.z; BsT[cs + 3][row] = bv.w;
    }
    __syncthreads();

    const int i0 = (t >> 4) * 4;
    const int j0 = (t & 15) * 4;
    float acc[4][4];
    #pragma unroll
    for (int a = 0; a < 4; a++)
        #pragma unroll
        for (int b2 = 0; b2 < 4; b2++) acc[a][b2] = 0.f;

    #pragma unroll 8
    for (int s = 0; s < 64; s++) {
        float4 a4 = *(const float4*)&AsT[s][i0];
        float4 b4 = *(const float4*)&BsT[s][j0];
        const float aa[4] = {a4.x, a4.y, a4.z, a4.w};
        const float bb[4] = {b4.x, b4.y, b4.z, b4.w};
        #pragma unroll
        for (int a = 0; a < 4; a++)
            #pragma unroll
            for (int b2 = 0; b2 < 4; b2++)
                acc[a][b2] += aa[a] * bb[b2];
    }

    #pragma unroll
    for (int a = 0; a < 4; a++) {
        *(float4*)&C[(size_t)(q0 + i0 + a) * NR + r0 + j0] =
            make_float4(acc[a][0], acc[a][1], acc[a][2], acc[a][3]);
    }
}

// ---------------------------------------------------------------------------
// Softmax with fused rel-shift gather. One block per (z, q) row.
// score[r] = (ct[r] + pp[r + 511 - q]) / 8 for r <= q+512; masked -> prob 0.
// Writes probs in-place into g_CT (full row of NR, zeros beyond rv).
// ---------------------------------------------------------------------------
__global__ __launch_bounds__(256)
void softmax_kernel()
{
    const int q = blockIdx.x;
    const int z = blockIdx.y;
    float* ct = g_CT + ((size_t)z * NQ + q) * NR;
    const float* pp = g_PP + ((size_t)z * NQ + q) * NR;
    const int rv = q + NM + 1;       // valid entries r in [0, rv)
    const int koff = NQ - 1 - q;     // k = r + koff

    __shared__ float sbuf[NR];
    __shared__ float redm[8], reds[8];
    const int t = threadIdx.x;
    const int lane = t & 31, warp = t >> 5;

    float m = -1e30f;
    for (int r = t; r < rv; r += 256) {
        const float v = (ct[r] + pp[r + koff]) * 0.125f;
        sbuf[r] = v;
        m = fmaxf(m, v);
    }
    #pragma unroll
    for (int o = 16; o; o >>= 1) m = fmaxf(m, __shfl_xor_sync(0xffffffffu, m, o));
    if (lane == 0) redm[warp] = m;
    __syncthreads();
    float mm = redm[0];
    #pragma unroll
    for (int w = 1; w < 8; w++) mm = fmaxf(mm, redm[w]);

    float sum = 0.f;
    for (int r = t; r < rv; r += 256) {
        const float e = expf(sbuf[r] - mm);
        sbuf[r] = e;
        sum += e;
    }
    #pragma unroll
    for (int o = 16; o; o >>= 1) sum += __shfl_xor_sync(0xffffffffu, sum, o);
    if (lane == 0) reds[warp] = sum;
    __syncthreads();
    float tot = 0.f;
    #pragma unroll
    for (int w = 0; w < 8; w++) tot += reds[w];
    const float inv = 1.f / tot;

    for (int r = t; r < NR; r += 256) {
        ct[r] = (r < rv) ? sbuf[r] * inv : 0.f;
    }
}

// ---------------------------------------------------------------------------
// AV GEMM: O[q, s] = sum_r P[q, r] * V[r, s] per z. 64(q) x 64(s) tile,
// K-loop truncated at q0+576 (probs are exactly 0 beyond the causal bound).
// ---------------------------------------------------------------------------
__global__ __launch_bounds__(256)
void av_kernel()
{
    const int q0 = blockIdx.x * 64;
    const int z  = blockIdx.y;
    const int bb = z >> 4, h = z & 15;
    const float* P = g_CT + (size_t)z * NQ * NR + (size_t)q0 * NR;
    const float* V = g_V + (size_t)z * NR * NS;

    __shared__ float PsT[64][68];  // [k][q]
    __shared__ float Vs[64][68];   // [k][s]

    const int t = threadIdx.x;
    const int row = t >> 2;        // 0..63
    const int i0 = (t >> 4) * 4;
    const int j0 = (t & 15) * 4;

    float acc[4][4];
    #pragma unroll
    for (int a = 0; a < 4; a++)
        #pragma unroll
        for (int b2 = 0; b2 < 4; b2++) acc[a][b2] = 0.f;

    const int kmax = q0 + 576;  // strictly > all unmasked r for this tile
    for (int k0 = 0; k0 < kmax; k0 += 64) {
        #pragma unroll
        for (int p = 0; p < 4; p++) {
            const int cs = ((t & 3) + p * 4) * 4;
            float4 pv = *(const float4*)(P + (size_t)row * NR + k0 + cs);
            PsT[cs + 0][row] = pv.x; PsT[cs + 1][row] = pv.y;
            PsT[cs + 2][row] = pv.z; PsT[cs + 3][row] = pv.w;
            float4 vv = *(const float4*)(V + (size_t)(k0 + row) * NS + cs);
            *(float4*)&Vs[row][cs] = vv;
        }
        __syncthreads();

        #pragma unroll 8
        for (int kk = 0; kk < 64; kk++) {
            float4 a4 = *(const float4*)&PsT[kk][i0];
            float4 b4 = *(const float4*)&Vs[kk][j0];
            const float aa[4] = {a4.x, a4.y, a4.z, a4.w};
            const float vv[4] = {b4.x, b4.y, b4.z, b4.w};
            #pragma unroll
            for (int a = 0; a < 4; a++)
                #pragma unroll
                for (int b2 = 0; b2 < 4; b2++)
                    acc[a][b2] += aa[a] * vv[b2];
        }
        __syncthreads();
    }

    #pragma unroll
    for (int a = 0; a < 4; a++) {
        const size_t o = (((size_t)(bb * NQ + q0 + i0 + a)) * NH + h) * NS + j0;
        *(float4*)&g_O[o] = make_float4(acc[a][0], acc[a][1], acc[a][2], acc[a][3]);
    }
}

// ---------------------------------------------------------------------------
extern "C" void kernel_launch(void* const* d_in, const int* in_sizes, int n_in,
                              void* d_out, int out_size)
{
    const float* qry = (const float*)d_in[0];   // [8,512,1024]
    const float* mem = (const float*)d_in[1];   // [8,512,1024]
    const float* pe  = (const float*)d_in[2];   // [1024,1024]
    // d_in[3] token_mask unused (analytic causal mask)
    const float* cb  = (const float*)d_in[4];   // [16,64]
    const float* pb  = (const float*)d_in[5];   // [16,64]
    const float* Wq  = (const float*)d_in[6];   // [1024,1024]
    const float* Wkc = (const float*)d_in[7];
    const float* Wkp = (const float*)d_in[8];
    const float* Wv  = (const float*)d_in[9];
    const float* Wo  = (const float*)d_in[10];  // [1024,1024] (h*64+s major)
    float* out = (float*)d_out;

    dim3 thr(256);

    // Projections
    gemm_nn<MODE_Q ><<<dim3(8, 32), thr>>>(qry, nullptr, Wq,  cb, pb, nullptr);
    gemm_nn<MODE_KC><<<dim3(8, 64), thr>>>(qry, mem,     Wkc, nullptr, nullptr, nullptr);
    gemm_nn<MODE_V ><<<dim3(8, 64), thr>>>(qry, mem,     Wv,  nullptr, nullptr, nullptr);
    gemm_nn<MODE_KP><<<dim3(8, 8),  thr>>>(pe,  nullptr, Wkp, nullptr, nullptr, nullptr);

    // Logits
    score_gemm<0><<<dim3(16, 8, NB * NH), thr>>>();
    score_gemm<1><<<dim3(16, 8, NB * NH), thr>>>();

    // Softmax (fused rel-shift + causal mask)
    softmax_kernel<<<dim3(NQ, NB * NH), thr>>>();

    // Attention * V
    av_kernel<<<dim3(8, NB * NH), thr>>>();

    // Output projection
    gemm_nn<MODE_OUT><<<dim3(8, 32), thr>>>(nullptr, nullptr, Wo, nullptr, nullptr, out);
}

// round 5
// speedup vs baseline: 2.8139x; 2.8139x over previous
#include <cuda_runtime.h>
#include <cuda_bf16.h>
#include <math.h>
#include <stdint.h>

// Problem constants
constexpr int NB = 8;     // batch
constexpr int NQ = 512;   // query len
constexpr int NM = 512;   // memory len
constexpr int NR = 1024;  // reference len
constexpr int NH = 16;    // heads
constexpr int NS = 64;    // size per head
constexpr int ND = 1024;  // hidden

#define ALGN __align__(16)

// fp32 scratch (attention core fp32)
__device__ ALGN float g_QC[(size_t)NB*NH*NQ*NS];
__device__ ALGN float g_QP[(size_t)NB*NH*NQ*NS];
__device__ ALGN float g_KC[(size_t)NB*NH*NR*NS];
__device__ ALGN float g_V [(size_t)NB*NH*NR*NS];
__device__ ALGN float g_KP[(size_t)NH*NR*NS];
__device__ ALGN float g_CT[(size_t)NB*NH*NQ*NR];
__device__ ALGN float g_PP[(size_t)NB*NH*NQ*NR];
__device__ ALGN float g_O [(size_t)NB*NQ*NH*NS];

// bf16 split scratch
__device__ ALGN __nv_bfloat16 g_XrefH[(size_t)NB*NR*ND];
__device__ ALGN __nv_bfloat16 g_XrefL[(size_t)NB*NR*ND];
__device__ ALGN __nv_bfloat16 g_PEH[(size_t)NR*ND];
__device__ ALGN __nv_bfloat16 g_PEL[(size_t)NR*ND];
__device__ ALGN __nv_bfloat16 g_OH[(size_t)NB*NQ*ND];
__device__ ALGN __nv_bfloat16 g_OL[(size_t)NB*NQ*ND];
// transposed weights Wt[c][k]: 0=Wq 1=Wkc 2=Wkp 3=Wv 4=Wo
__device__ ALGN __nv_bfloat16 g_WtH[5][(size_t)ND*ND];
__device__ ALGN __nv_bfloat16 g_WtL[5][(size_t)ND*ND];

enum { MODE_Q = 0, MODE_KC = 1, MODE_V = 2, MODE_KP = 3, MODE_OUT = 4 };

// ---------------------------------------------------------------------------
// helpers
// ---------------------------------------------------------------------------
__device__ __forceinline__ uint32_t smem_u32(const void* p) {
    uint32_t a;
    asm("{ .reg .u64 t; cvta.to.shared.u64 t, %1; cvt.u32.u64 %0, t; }"
        : "=r"(a) : "l"(p));
    return a;
}
__device__ __forceinline__ void cp16(uint32_t dst, const void* src) {
    asm volatile("cp.async.cg.shared.global [%0], [%1], 16;"
                 :: "r"(dst), "l"(src) : "memory");
}
__device__ __forceinline__ void ldsm_x4(uint32_t* r, uint32_t addr) {
    asm volatile("ldmatrix.sync.aligned.m8n8.x4.shared.b16 {%0,%1,%2,%3}, [%4];"
                 : "=r"(r[0]), "=r"(r[1]), "=r"(r[2]), "=r"(r[3]) : "r"(addr));
}
__device__ __forceinline__ void mma16816(float* c, const uint32_t* a, const uint32_t* b) {
    asm volatile(
        "mma.sync.aligned.m16n8k16.row.col.f32.bf16.bf16.f32 "
        "{%0,%1,%2,%3}, {%4,%5,%6,%7}, {%8,%9}, {%0,%1,%2,%3};"
        : "+f"(c[0]), "+f"(c[1]), "+f"(c[2]), "+f"(c[3])
        : "r"(a[0]), "r"(a[1]), "r"(a[2]), "r"(a[3]), "r"(b[0]), "r"(b[1]));
}
#define SWZ64(x) ((x) ^ (((x) >> 3) & 0x30))

// ---------------------------------------------------------------------------
// Conversion kernels
// ---------------------------------------------------------------------------
__device__ __forceinline__ void split1(float v, __nv_bfloat16& h, __nv_bfloat16& l) {
    h = __float2bfloat16(v);
    l = __float2bfloat16(v - __bfloat162float(h));
}

__global__ void conv_xref(const float* __restrict__ qry, const float* __restrict__ mem) {
    const int row = blockIdx.x;
    const int b = row >> 10, r = row & 1023;
    const float* src = (r < NM) ? mem + ((size_t)(b * NM + r)) * ND
                                : qry + ((size_t)(b * NQ + (r - NM))) * ND;
    const int c = threadIdx.x * 4;
    float4 v = *(const float4*)(src + c);
    const size_t o = (size_t)row * ND + c;
    split1(v.x, g_XrefH[o+0], g_XrefL[o+0]);
    split1(v.y, g_XrefH[o+1], g_XrefL[o+1]);
    split1(v.z, g_XrefH[o+2], g_XrefL[o+2]);
    split1(v.w, g_XrefH[o+3], g_XrefL[o+3]);
}

template <int WHICH>  // 0 = PE, 1 = O
__global__ void conv_plain(const float* __restrict__ src) {
    const size_t i = (size_t)blockIdx.x * blockDim.x + threadIdx.x;
    float v = (WHICH == 0) ? src[i] : g_O[i];
    __nv_bfloat16 h, l;
    split1(v, h, l);
    if (WHICH == 0) { g_PEH[i] = h; g_PEL[i] = l; }
    else            { g_OH[i]  = h; g_OL[i]  = l; }
}

template <int WID>
__global__ void conv_wt(const float* __restrict__ W) {
    __shared__ float tile[32][33];
    const int c0 = blockIdx.x * 32, k0 = blockIdx.y * 32;
    const int tx = threadIdx.x, ty = threadIdx.y;  // 32 x 8
    for (int i = ty; i < 32; i += 8)
        tile[i][tx] = W[(size_t)(k0 + i) * ND + c0 + tx];
    __syncthreads();
    for (int i = ty; i < 32; i += 8) {
        float v = tile[tx][i];
        __nv_bfloat16 h, l;
        split1(v, h, l);
        const size_t o = (size_t)(c0 + i) * ND + k0 + tx;
        g_WtH[WID][o] = h;
        g_WtL[WID][o] = l;
    }
}

// ---------------------------------------------------------------------------
// Split-bf16 mma.sync projection GEMM (3-pass: AhBh + AhBl + AlBh).
// C[m0:128, n0:128] = A[rows, 1024] * Wt[cols, 1024]^T, both K-major bf16.
// 256 threads = 8 warps; warp tile 32(m) x 64(n); m16n8k16.
// Smem: 4 tiles (Ah,Al,Bh,Bl) of 128x32 bf16 = 8KB each, SW64 swizzle,
// 2-stage cp.async double buffer. 32 K-chunks of 32 elements cover ND=1024.
// ---------------------------------------------------------------------------
constexpr int TILEB  = 128 * 64;      // 8192 B per matrix tile
constexpr int STAGEB = 4 * TILEB;     // 32768
constexpr int GSMEM  = 2 * STAGEB + 1024;
constexpr int NCHUNK = ND / 32;       // 32 chunks of K=32

template <int MODE>
__global__ __launch_bounds__(256)
void mma_gemm(const float* __restrict__ cb, const float* __restrict__ pb,
              float* __restrict__ outp)
{
    extern __shared__ char dsm[];
    const uint32_t dyn_u32 = smem_u32(dsm);
    const uint32_t base = (dyn_u32 + 1023u) & ~1023u;
    float* stg = reinterpret_cast<float*>(dsm + (base - dyn_u32));

    const int t = threadIdx.x;
    const int wid = t >> 5, lane = t & 31;
    const int n0 = blockIdx.x * 128;
    const int m0 = blockIdx.y * 128;
    const int arow0 = (MODE == MODE_Q) ? ((m0 >> 9) * 1024 + 512 + (m0 & 511)) : m0;

    const __nv_bfloat16 *Ah, *Al, *Bh, *Bl;
    if (MODE == MODE_Q)       { Ah = g_XrefH; Al = g_XrefL; Bh = g_WtH[0]; Bl = g_WtL[0]; }
    else if (MODE == MODE_KC) { Ah = g_XrefH; Al = g_XrefL; Bh = g_WtH[1]; Bl = g_WtL[1]; }
    else if (MODE == MODE_KP) { Ah = g_PEH;   Al = g_PEL;   Bh = g_WtH[2]; Bl = g_WtL[2]; }
    else if (MODE == MODE_V)  { Ah = g_XrefH; Al = g_XrefL; Bh = g_WtH[3]; Bl = g_WtL[3]; }
    else                      { Ah = g_OH;    Al = g_OL;    Bh = g_WtH[4]; Bl = g_WtL[4]; }

    // load mapping: thread handles 2 16B segments per matrix per stage
    const int s0 = t;
    const int mseg0 = s0 >> 2, cseg0 = s0 & 3;
    const int s1 = t + 256;
    const int mseg1 = s1 >> 2, cseg1 = s1 & 3;

    auto load_stage = [&](int chunk, int buf) {
        const uint32_t sb = base + buf * STAGEB;
        const int kbyte = chunk * 64;  // 32 bf16 = 64B per chunk
        {
            const char* a0 = (const char*)(Ah + (size_t)(arow0 + mseg0) * ND) + kbyte + cseg0 * 16;
            const char* a1 = (const char*)(Al + (size_t)(arow0 + mseg0) * ND) + kbyte + cseg0 * 16;
            const char* b0 = (const char*)(Bh + (size_t)(n0 + mseg0) * ND) + kbyte + cseg0 * 16;
            const char* b1 = (const char*)(Bl + (size_t)(n0 + mseg0) * ND) + kbyte + cseg0 * 16;
            const uint32_t sw = SWZ64((uint32_t)(mseg0 * 64 + cseg0 * 16));
            cp16(sb + 0 * TILEB + sw, a0);
            cp16(sb + 1 * TILEB + sw, a1);
            cp16(sb + 2 * TILEB + sw, b0);
            cp16(sb + 3 * TILEB + sw, b1);
        }
        {
            const char* a0 = (const char*)(Ah + (size_t)(arow0 + mseg1) * ND) + kbyte + cseg1 * 16;
            const char* a1 = (const char*)(Al + (size_t)(arow0 + mseg1) * ND) + kbyte + cseg1 * 16;
            const char* b0 = (const char*)(Bh + (size_t)(n0 + mseg1) * ND) + kbyte + cseg1 * 16;
            const char* b1 = (const char*)(Bl + (size_t)(n0 + mseg1) * ND) + kbyte + cseg1 * 16;
            const uint32_t sw = SWZ64((uint32_t)(mseg1 * 64 + cseg1 * 16));
            cp16(sb + 0 * TILEB + sw, a0);
            cp16(sb + 1 * TILEB + sw, a1);
            cp16(sb + 2 * TILEB + sw, b0);
            cp16(sb + 3 * TILEB + sw, b1);
        }
        asm volatile("cp.async.commit_group;" ::: "memory");
    };

    // warp tiling
    const int wm = wid >> 1;
    const int wn = wid & 1;
    const int mbase = wm * 32;
    const int nbase = wn * 64;

    // ldmatrix per-lane address components
    const int tle = lane >> 3;
    const int rin = lane & 7;
    const int a_moff = rin + (tle & 1) * 8;
    const int a_koff = (tle >> 1) * 16;     // bytes
    const int b_noff = (tle < 2) ? rin : (rin + 8);
    const int b_koff = (tle & 1) * 16;      // bytes

    float acc[2][8][4];
    #pragma unroll
    for (int i = 0; i < 2; i++)
        #pragma unroll
        for (int j = 0; j < 8; j++)
            #pragma unroll
            for (int k = 0; k < 4; k++) acc[i][j][k] = 0.f;

    auto compute_stage = [&](int buf) {
        const uint32_t sb = base + buf * STAGEB;
        #pragma unroll
        for (int ks = 0; ks < 2; ks++) {
            uint32_t ah[2][4], al[2][4], bh[4][4], bl[4][4];
            #pragma unroll
            for (int i = 0; i < 2; i++) {
                const uint32_t off = SWZ64((uint32_t)((mbase + 16 * i + a_moff) * 64 + ks * 32 + a_koff));
                ldsm_x4(ah[i], sb + 0 * TILEB + off);
                ldsm_x4(al[i], sb + 1 * TILEB + off);
            }
            #pragma unroll
            for (int jp = 0; jp < 4; jp++) {
                const uint32_t off = SWZ64((uint32_t)((nbase + 16 * jp + b_noff) * 64 + ks * 32 + b_koff));
                ldsm_x4(bh[jp], sb + 2 * TILEB + off);
                ldsm_x4(bl[jp], sb + 3 * TILEB + off);
            }
            #pragma unroll
            for (int i = 0; i < 2; i++) {
                #pragma unroll
                for (int j = 0; j < 8; j++) {
                    const uint32_t* bf = &bh[j >> 1][(j & 1) * 2];
                    mma16816(acc[i][j], ah[i], bf);
                }
                #pragma unroll
                for (int j = 0; j < 8; j++) {
                    const uint32_t* bf = &bl[j >> 1][(j & 1) * 2];
                    mma16816(acc[i][j], ah[i], bf);
                }
                #pragma unroll
                for (int j = 0; j < 8; j++) {
                    const uint32_t* bf = &bh[j >> 1][(j & 1) * 2];
                    mma16816(acc[i][j], al[i], bf);
                }
            }
        }
    };

    // pipeline over FULL K = 1024 (32 chunks of 32 elements)
    load_stage(0, 0);
    for (int c = 0; c < NCHUNK; c++) {
        const int buf = c & 1;
        if (c + 1 < NCHUNK) {
            load_stage(c + 1, buf ^ 1);
            asm volatile("cp.async.wait_group 1;" ::: "memory");
        } else {
            asm volatile("cp.async.wait_group 0;" ::: "memory");
        }
        __syncthreads();
        compute_stage(buf);
        __syncthreads();
    }

    // Epilogue: stage 64 rows at a time into smem (stride 132), scatter to gmem
    const int lr = lane >> 2;
    const int lc = (lane & 3) * 2;
    for (int p = 0; p < 2; p++) {
        if ((wm >> 1) == p) {
            const int rb = mbase - p * 64;
            #pragma unroll
            for (int i = 0; i < 2; i++) {
                #pragma unroll
                for (int j = 0; j < 8; j++) {
                    const int rr = rb + 16 * i + lr;
                    const int cc = nbase + 8 * j + lc;
                    *(float2*)&stg[rr * 132 + cc]       = make_float2(acc[i][j][0], acc[i][j][1]);
                    *(float2*)&stg[(rr + 8) * 132 + cc] = make_float2(acc[i][j][2], acc[i][j][3]);
                }
            }
        }
        __syncthreads();
        {
            const int rl = t >> 2;
            const int quad = t & 3;
            const int grow = m0 + 64 * p + rl;
            const int cq = quad * 32;
            const float* sp = stg + rl * 132 + cq;
            if (MODE == MODE_Q) {
                const int b = grow >> 9, q = grow & 511;
                const int h = (n0 + cq) >> 6, sO = (n0 + cq) & 63;
                float* d1 = g_QC + (((size_t)(b * NH + h)) * NQ + q) * NS + sO;
                float* d2 = g_QP + (((size_t)(b * NH + h)) * NQ + q) * NS + sO;
                const float* cbp = cb + n0 + cq;
                const float* pbp = pb + n0 + cq;
                #pragma unroll
                for (int j = 0; j < 32; j += 4) {
                    float4 v = make_float4(sp[j], sp[j+1], sp[j+2], sp[j+3]);
                    *(float4*)(d1 + j) = make_float4(v.x + cbp[j], v.y + cbp[j+1],
                                                     v.z + cbp[j+2], v.w + cbp[j+3]);
                    *(float4*)(d2 + j) = make_float4(v.x + pbp[j], v.y + pbp[j+1],
                                                     v.z + pbp[j+2], v.w + pbp[j+3]);
                }
            } else if (MODE == MODE_KC || MODE == MODE_V) {
                const int b = grow >> 10, r = grow & 1023;
                const int h = (n0 + cq) >> 6, sO = (n0 + cq) & 63;
                float* d1 = (MODE == MODE_KC ? g_KC : g_V) +
                            (((size_t)(b * NH + h)) * NR + r) * NS + sO;
                #pragma unroll
                for (int j = 0; j < 32; j += 4)
                    *(float4*)(d1 + j) = make_float4(sp[j], sp[j+1], sp[j+2], sp[j+3]);
            } else if (MODE == MODE_KP) {
                const int h = (n0 + cq) >> 6, sO = (n0 + cq) & 63;
                float* d1 = g_KP + ((size_t)h * NR + grow) * NS + sO;
                #pragma unroll
                for (int j = 0; j < 32; j += 4)
                    *(float4*)(d1 + j) = make_float4(sp[j], sp[j+1], sp[j+2], sp[j+3]);
            } else {
                float* d1 = outp + (size_t)grow * ND + n0 + cq;
                #pragma unroll
                for (int j = 0; j < 32; j += 4)
                    *(float4*)(d1 + j) = make_float4(sp[j], sp[j+1], sp[j+2], sp[j+3]);
            }
        }
        __syncthreads();
    }
}

// ---------------------------------------------------------------------------
// Score GEMM (fp32, round-1 proven)
// ---------------------------------------------------------------------------
template <int PPMODE>
__global__ __launch_bounds__(256)
void score_gemm()
{
    const int z  = blockIdx.z;
    const int q0 = blockIdx.y * 64;
    const int r0 = blockIdx.x * 64;

    if (PPMODE == 0) {
        if (r0 >= q0 + 576) return;
    } else {
        if (r0 + 63 < 448 - q0) return;
    }

    __shared__ float AsT[64][68];
    __shared__ float BsT[64][68];

    const int t = threadIdx.x;
    const float* A = (PPMODE ? g_QP : g_QC) + (size_t)z * NQ * NS + (size_t)q0 * NS;
    const float* B = PPMODE ? (g_KP + (size_t)(z & (NH - 1)) * NR * NS + (size_t)r0 * NS)
                            : (g_KC + (size_t)z * NR * NS + (size_t)r0 * NS);
    float* C = (PPMODE ? g_PP : g_CT) + (size_t)z * NQ * NR;

    const int row = t >> 2;
    #pragma unroll
    for (int p = 0; p < 4; p++) {
        const int cs = ((t & 3) + p * 4) * 4;
        float4 av = *(const float4*)(A + (size_t)row * NS + cs);
        float4 bv = *(const float4*)(B + (size_t)row * NS + cs);
        AsT[cs + 0][row] = av.x; AsT[cs + 1][row] = av.y;
        AsT[cs + 2][row] = av.z; AsT[cs + 3][row] = av.w;
        BsT[cs + 0][row] = bv.x; BsT[cs + 1][row] = bv.y;
        BsT[cs + 2][row] = bv.z; BsT[cs + 3][row] = bv.w;
    }
    __syncthreads();

    const int i0 = (t >> 4) * 4;
    const int j0 = (t & 15) * 4;
    float acc[4][4];
    #pragma unroll
    for (int a = 0; a < 4; a++)
        #pragma unroll
        for (int b2 = 0; b2 < 4; b2++) acc[a][b2] = 0.f;

    #pragma unroll 8
    for (int s = 0; s < 64; s++) {
        float4 a4 = *(const float4*)&AsT[s][i0];
        float4 b4 = *(const float4*)&BsT[s][j0];
        const float aa[4] = {a4.x, a4.y, a4.z, a4.w};
        const float bb[4] = {b4.x, b4.y, b4.z, b4.w};
        #pragma unroll
        for (int a = 0; a < 4; a++)
            #pragma unroll
            for (int b2 = 0; b2 < 4; b2++)
                acc[a][b2] += aa[a] * bb[b2];
    }

    #pragma unroll
    for (int a = 0; a < 4; a++) {
        *(float4*)&C[(size_t)(q0 + i0 + a) * NR + r0 + j0] =
            make_float4(acc[a][0], acc[a][1], acc[a][2], acc[a][3]);
    }
}

// ---------------------------------------------------------------------------
// Softmax with fused rel-shift gather
// ---------------------------------------------------------------------------
__global__ __launch_bounds__(256)
void softmax_kernel()
{
    const int q = blockIdx.x;
    const int z = blockIdx.y;
    float* ct = g_CT + ((size_t)z * NQ + q) * NR;
    const float* pp = g_PP + ((size_t)z * NQ + q) * NR;
    const int rv = q + NM + 1;
    const int koff = NQ - 1 - q;

    __shared__ float sbuf[NR];
    __shared__ float redm[8], reds[8];
    const int t = threadIdx.x;
    const int lane = t & 31, warp = t >> 5;

    float m = -1e30f;
    for (int r = t; r < rv; r += 256) {
        const float v = (ct[r] + pp[r + koff]) * 0.125f;
        sbuf[r] = v;
        m = fmaxf(m, v);
    }
    #pragma unroll
    for (int o = 16; o; o >>= 1) m = fmaxf(m, __shfl_xor_sync(0xffffffffu, m, o));
    if (lane == 0) redm[warp] = m;
    __syncthreads();
    float mm = redm[0];
    #pragma unroll
    for (int w = 1; w < 8; w++) mm = fmaxf(mm, redm[w]);

    float sum = 0.f;
    for (int r = t; r < rv; r += 256) {
        const float e = expf(sbuf[r] - mm);
        sbuf[r] = e;
        sum += e;
    }
    #pragma unroll
    for (int o = 16; o; o >>= 1) sum += __shfl_xor_sync(0xffffffffu, sum, o);
    if (lane == 0) reds[warp] = sum;
    __syncthreads();
    float tot = 0.f;
    #pragma unroll
    for (int w = 0; w < 8; w++) tot += reds[w];
    const float inv = 1.f / tot;

    for (int r = t; r < NR; r += 256) {
        ct[r] = (r < rv) ? sbuf[r] * inv : 0.f;
    }
}

// ---------------------------------------------------------------------------
// AV GEMM (fp32)
// ---------------------------------------------------------------------------
__global__ __launch_bounds__(256)
void av_kernel()
{
    const int q0 = blockIdx.x * 64;
    const int z  = blockIdx.y;
    const int bb = z >> 4, h = z & 15;
    const float* P = g_CT + (size_t)z * NQ * NR + (size_t)q0 * NR;
    const float* V = g_V + (size_t)z * NR * NS;

    __shared__ float PsT[64][68];
    __shared__ float Vs[64][68];

    const int t = threadIdx.x;
    const int row = t >> 2;
    const int i0 = (t >> 4) * 4;
    const int j0 = (t & 15) * 4;

    float acc[4][4];
    #pragma unroll
    for (int a = 0; a < 4; a++)
        #pragma unroll
        for (int b2 = 0; b2 < 4; b2++) acc[a][b2] = 0.f;

    const int kmax = q0 + 576;
    for (int k0 = 0; k0 < kmax; k0 += 64) {
        #pragma unroll
        for (int p = 0; p < 4; p++) {
            const int cs = ((t & 3) + p * 4) * 4;
            float4 pv = *(const float4*)(P + (size_t)row * NR + k0 + cs);
            PsT[cs + 0][row] = pv.x; PsT[cs + 1][row] = pv.y;
            PsT[cs + 2][row] = pv.z; PsT[cs + 3][row] = pv.w;
            float4 vv = *(const float4*)(V + (size_t)(k0 + row) * NS + cs);
            *(float4*)&Vs[row][cs] = vv;
        }
        __syncthreads();

        #pragma unroll 8
        for (int kk = 0; kk < 64; kk++) {
            float4 a4 = *(const float4*)&PsT[kk][i0];
            float4 b4 = *(const float4*)&Vs[kk][j0];
            const float aa[4] = {a4.x, a4.y, a4.z, a4.w};
            const float vv[4] = {b4.x, b4.y, b4.z, b4.w};
            #pragma unroll
            for (int a = 0; a < 4; a++)
                #pragma unroll
                for (int b2 = 0; b2 < 4; b2++)
                    acc[a][b2] += aa[a] * vv[b2];
        }
        __syncthreads();
    }

    #pragma unroll
    for (int a = 0; a < 4; a++) {
        const size_t o = (((size_t)(bb * NQ + q0 + i0 + a)) * NH + h) * NS + j0;
        *(float4*)&g_O[o] = make_float4(acc[a][0], acc[a][1], acc[a][2], acc[a][3]);
    }
}

// ---------------------------------------------------------------------------
extern "C" void kernel_launch(void* const* d_in, const int* in_sizes, int n_in,
                              void* d_out, int out_size)
{
    const float* qry = (const float*)d_in[0];
    const float* mem = (const float*)d_in[1];
    const float* pe  = (const float*)d_in[2];
    const float* cb  = (const float*)d_in[4];
    const float* pb  = (const float*)d_in[5];
    const float* Wq  = (const float*)d_in[6];
    const float* Wkc = (const float*)d_in[7];
    const float* Wkp = (const float*)d_in[8];
    const float* Wv  = (const float*)d_in[9];
    const float* Wo  = (const float*)d_in[10];
    float* out = (float*)d_out;

    cudaFuncSetAttribute(mma_gemm<MODE_Q>,   cudaFuncAttributeMaxDynamicSharedMemorySize, GSMEM);
    cudaFuncSetAttribute(mma_gemm<MODE_KC>,  cudaFuncAttributeMaxDynamicSharedMemorySize, GSMEM);
    cudaFuncSetAttribute(mma_gemm<MODE_V>,   cudaFuncAttributeMaxDynamicSharedMemorySize, GSMEM);
    cudaFuncSetAttribute(mma_gemm<MODE_KP>,  cudaFuncAttributeMaxDynamicSharedMemorySize, GSMEM);
    cudaFuncSetAttribute(mma_gemm<MODE_OUT>, cudaFuncAttributeMaxDynamicSharedMemorySize, GSMEM);

    dim3 thr(256);
    dim3 wtb(32, 8);

    // conversions
    conv_xref<<<NB * NR, 256>>>(qry, mem);
    conv_plain<0><<<(NR * ND) / 256, 256>>>(pe);
    conv_wt<0><<<dim3(32, 32), wtb>>>(Wq);
    conv_wt<1><<<dim3(32, 32), wtb>>>(Wkc);
    conv_wt<2><<<dim3(32, 32), wtb>>>(Wkp);
    conv_wt<3><<<dim3(32, 32), wtb>>>(Wv);
    conv_wt<4><<<dim3(32, 32), wtb>>>(Wo);

    // tensor-core projections (split bf16 mma.sync)
    mma_gemm<MODE_Q ><<<dim3(8, 32), thr, GSMEM>>>(cb, pb, nullptr);
    mma_gemm<MODE_KC><<<dim3(8, 64), thr, GSMEM>>>(nullptr, nullptr, nullptr);
    mma_gemm<MODE_V ><<<dim3(8, 64), thr, GSMEM>>>(nullptr, nullptr, nullptr);
    mma_gemm<MODE_KP><<<dim3(8, 8),  thr, GSMEM>>>(nullptr, nullptr, nullptr);

    // attention core (fp32)
    score_gemm<0><<<dim3(16, 8, NB * NH), thr>>>();
    score_gemm<1><<<dim3(16, 8, NB * NH), thr>>>();
    softmax_kernel<<<dim3(NQ, NB * NH), thr>>>();
    av_kernel<<<dim3(8, NB * NH), thr>>>();

    // output projection
    conv_plain<1><<<(NB * NQ * ND) / 256, 256>>>(nullptr);
    mma_gemm<MODE_OUT><<<dim3(8, 32), thr, GSMEM>>>(nullptr, nullptr, out);
}

// round 7
// speedup vs baseline: 3.9813x; 1.4149x over previous
#include <cuda_runtime.h>
#include <cuda_bf16.h>
#include <math.h>
#include <stdint.h>

// Problem constants
constexpr int NB = 8;     // batch
constexpr int NQ = 512;   // query len
constexpr int NM = 512;   // memory len
constexpr int NR = 1024;  // reference len
constexpr int NH = 16;    // heads
constexpr int NS = 64;    // size per head
constexpr int ND = 1024;  // hidden

#define ALGN __align__(16)

// fp32 logits
__device__ ALGN float g_CT[(size_t)NB*NH*NQ*NR];   // content logits
__device__ ALGN float g_PP[(size_t)NB*NH*NQ*NR];   // positional logits (k index)

// bf16 split attention operands (written by projection epilogues)
__device__ ALGN __nv_bfloat16 g_QCh[(size_t)NB*NH*NQ*NS];
__device__ ALGN __nv_bfloat16 g_QCl[(size_t)NB*NH*NQ*NS];
__device__ ALGN __nv_bfloat16 g_QPh[(size_t)NB*NH*NQ*NS];
__device__ ALGN __nv_bfloat16 g_QPl[(size_t)NB*NH*NQ*NS];
__device__ ALGN __nv_bfloat16 g_KCh[(size_t)NB*NH*NR*NS];
__device__ ALGN __nv_bfloat16 g_KCl[(size_t)NB*NH*NR*NS];
__device__ ALGN __nv_bfloat16 g_KPh[(size_t)NH*NR*NS];
__device__ ALGN __nv_bfloat16 g_KPl[(size_t)NH*NR*NS];
__device__ ALGN __nv_bfloat16 g_VtH[(size_t)NB*NH*NS*NR];  // V transposed [z][s][r]
__device__ ALGN __nv_bfloat16 g_VtL[(size_t)NB*NH*NS*NR];
// probs (bf16 split, written by softmax)
__device__ ALGN __nv_bfloat16 g_Ph[(size_t)NB*NH*NQ*NR];
__device__ ALGN __nv_bfloat16 g_Pl[(size_t)NB*NH*NQ*NR];
// attention output (bf16 split, written by av_mma)
__device__ ALGN __nv_bfloat16 g_OH[(size_t)NB*NQ*ND];
__device__ ALGN __nv_bfloat16 g_OL[(size_t)NB*NQ*ND];

// bf16 split inputs for projections
__device__ ALGN __nv_bfloat16 g_XrefH[(size_t)NB*NR*ND];
__device__ ALGN __nv_bfloat16 g_XrefL[(size_t)NB*NR*ND];
__device__ ALGN __nv_bfloat16 g_PEH[(size_t)NR*ND];
__device__ ALGN __nv_bfloat16 g_PEL[(size_t)NR*ND];
// transposed weights Wt[c][k]: 0=Wq 1=Wkc 2=Wkp 3=Wv 4=Wo
__device__ ALGN __nv_bfloat16 g_WtH[5][(size_t)ND*ND];
__device__ ALGN __nv_bfloat16 g_WtL[5][(size_t)ND*ND];

enum { MODE_Q = 0, MODE_KC = 1, MODE_V = 2, MODE_KP = 3, MODE_OUT = 4 };

// ---------------------------------------------------------------------------
// helpers
// ---------------------------------------------------------------------------
__device__ __forceinline__ uint32_t smem_u32(const void* p) {
    uint32_t a;
    asm("{ .reg .u64 t; cvta.to.shared.u64 t, %1; cvt.u32.u64 %0, t; }"
        : "=r"(a) : "l"(p));
    return a;
}
__device__ __forceinline__ void cp16(uint32_t dst, const void* src) {
    asm volatile("cp.async.cg.shared.global [%0], [%1], 16;"
                 :: "r"(dst), "l"(src) : "memory");
}
__device__ __forceinline__ void ldsm_x4(uint32_t* r, uint32_t addr) {
    asm volatile("ldmatrix.sync.aligned.m8n8.x4.shared.b16 {%0,%1,%2,%3}, [%4];"
                 : "=r"(r[0]), "=r"(r[1]), "=r"(r[2]), "=r"(r[3]) : "r"(addr));
}
__device__ __forceinline__ void mma16816(float* c, const uint32_t* a, const uint32_t* b) {
    asm volatile(
        "mma.sync.aligned.m16n8k16.row.col.f32.bf16.bf16.f32 "
        "{%0,%1,%2,%3}, {%4,%5,%6,%7}, {%8,%9}, {%0,%1,%2,%3};"
        : "+f"(c[0]), "+f"(c[1]), "+f"(c[2]), "+f"(c[3])
        : "r"(a[0]), "r"(a[1]), "r"(a[2]), "r"(a[3]), "r"(b[0]), "r"(b[1]));
}
#define SWZ64(x)  ((x) ^ (((x) >> 3) & 0x30))
#define SWZ128(x) ((x) ^ (((x) >> 3) & 0x70))

__device__ __forceinline__ void split1(float v, __nv_bfloat16& h, __nv_bfloat16& l) {
    h = __float2bfloat16(v);
    l = __float2bfloat16(v - __bfloat162float(h));
}
__device__ __forceinline__ void store_split2(__nv_bfloat16* ph, __nv_bfloat16* pl,
                                             float a, float b) {
    __nv_bfloat162 hh, ll;
    hh.x = __float2bfloat16(a);
    ll.x = __float2bfloat16(a - __bfloat162float(hh.x));
    hh.y = __float2bfloat16(b);
    ll.y = __float2bfloat16(b - __bfloat162float(hh.y));
    *(__nv_bfloat162*)ph = hh;
    *(__nv_bfloat162*)pl = ll;
}

// ---------------------------------------------------------------------------
// Conversion kernels
// ---------------------------------------------------------------------------
__global__ void conv_xref(const float* __restrict__ qry, const float* __restrict__ mem) {
    const int row = blockIdx.x;
    const int b = row >> 10, r = row & 1023;
    const float* src = (r < NM) ? mem + ((size_t)(b * NM + r)) * ND
                                : qry + ((size_t)(b * NQ + (r - NM))) * ND;
    const int c = threadIdx.x * 4;
    float4 v = *(const float4*)(src + c);
    const size_t o = (size_t)row * ND + c;
    split1(v.x, g_XrefH[o+0], g_XrefL[o+0]);
    split1(v.y, g_XrefH[o+1], g_XrefL[o+1]);
    split1(v.z, g_XrefH[o+2], g_XrefL[o+2]);
    split1(v.w, g_XrefH[o+3], g_XrefL[o+3]);
}

__global__ void conv_pe(const float* __restrict__ src) {
    const size_t i = (size_t)blockIdx.x * blockDim.x + threadIdx.x;
    split1(src[i], g_PEH[i], g_PEL[i]);
}

template <int WID>
__global__ void conv_wt(const float* __restrict__ W) {
    __shared__ float tile[32][33];
    const int c0 = blockIdx.x * 32, k0 = blockIdx.y * 32;
    const int tx = threadIdx.x, ty = threadIdx.y;  // 32 x 8
    for (int i = ty; i < 32; i += 8)
        tile[i][tx] = W[(size_t)(k0 + i) * ND + c0 + tx];
    __syncthreads();
    for (int i = ty; i < 32; i += 8) {
        float v = tile[tx][i];
        __nv_bfloat16 h, l;
        split1(v, h, l);
        const size_t o = (size_t)(c0 + i) * ND + k0 + tx;
        g_WtH[WID][o] = h;
        g_WtL[WID][o] = l;
    }
}

// ---------------------------------------------------------------------------
// Split-bf16 mma.sync projection GEMM (3-pass: AhBh + AhBl + AlBh).
// 128x128 tile, K=1024, 8 warps, warp tile 32x64, 2-stage cp.async.
// Epilogues write bf16-split attention operands (or fp32 for MODE_OUT).
// ---------------------------------------------------------------------------
constexpr int TILEB  = 128 * 64;      // 8192 B per matrix tile (128 rows x 64B)
constexpr int STAGEB = 4 * TILEB;
constexpr int GSMEM  = 2 * STAGEB + 1024;
constexpr int NCHUNK = ND / 32;       // 32 chunks of K=32

template <int MODE>
__global__ __launch_bounds__(256)
void mma_gemm(const float* __restrict__ cb, const float* __restrict__ pb,
              float* __restrict__ outp)
{
    extern __shared__ char dsm[];
    const uint32_t dyn_u32 = smem_u32(dsm);
    const uint32_t base = (dyn_u32 + 1023u) & ~1023u;
    float* stg = reinterpret_cast<float*>(dsm + (base - dyn_u32));

    const int t = threadIdx.x;
    const int wid = t >> 5, lane = t & 31;
    const int n0 = blockIdx.x * 128;
    const int m0 = blockIdx.y * 128;
    const int arow0 = (MODE == MODE_Q) ? ((m0 >> 9) * 1024 + 512 + (m0 & 511)) : m0;

    const __nv_bfloat16 *Ah, *Al, *Bh, *Bl;
    if (MODE == MODE_Q)       { Ah = g_XrefH; Al = g_XrefL; Bh = g_WtH[0]; Bl = g_WtL[0]; }
    else if (MODE == MODE_KC) { Ah = g_XrefH; Al = g_XrefL; Bh = g_WtH[1]; Bl = g_WtL[1]; }
    else if (MODE == MODE_KP) { Ah = g_PEH;   Al = g_PEL;   Bh = g_WtH[2]; Bl = g_WtL[2]; }
    else if (MODE == MODE_V)  { Ah = g_XrefH; Al = g_XrefL; Bh = g_WtH[3]; Bl = g_WtL[3]; }
    else                      { Ah = g_OH;    Al = g_OL;    Bh = g_WtH[4]; Bl = g_WtL[4]; }

    const int s0 = t;
    const int mseg0 = s0 >> 2, cseg0 = s0 & 3;
    const int s1 = t + 256;
    const int mseg1 = s1 >> 2, cseg1 = s1 & 3;

    auto load_stage = [&](int chunk, int buf) {
        const uint32_t sb = base + buf * STAGEB;
        const int kbyte = chunk * 64;
        {
            const char* a0 = (const char*)(Ah + (size_t)(arow0 + mseg0) * ND) + kbyte + cseg0 * 16;
            const char* a1 = (const char*)(Al + (size_t)(arow0 + mseg0) * ND) + kbyte + cseg0 * 16;
            const char* b0 = (const char*)(Bh + (size_t)(n0 + mseg0) * ND) + kbyte + cseg0 * 16;
            const char* b1 = (const char*)(Bl + (size_t)(n0 + mseg0) * ND) + kbyte + cseg0 * 16;
            const uint32_t sw = SWZ64((uint32_t)(mseg0 * 64 + cseg0 * 16));
            cp16(sb + 0 * TILEB + sw, a0);
            cp16(sb + 1 * TILEB + sw, a1);
            cp16(sb + 2 * TILEB + sw, b0);
            cp16(sb + 3 * TILEB + sw, b1);
        }
        {
            const char* a0 = (const char*)(Ah + (size_t)(arow0 + mseg1) * ND) + kbyte + cseg1 * 16;
            const char* a1 = (const char*)(Al + (size_t)(arow0 + mseg1) * ND) + kbyte + cseg1 * 16;
            const char* b0 = (const char*)(Bh + (size_t)(n0 + mseg1) * ND) + kbyte + cseg1 * 16;
            const char* b1 = (const char*)(Bl + (size_t)(n0 + mseg1) * ND) + kbyte + cseg1 * 16;
            const uint32_t sw = SWZ64((uint32_t)(mseg1 * 64 + cseg1 * 16));
            cp16(sb + 0 * TILEB + sw, a0);
            cp16(sb + 1 * TILEB + sw, a1);
            cp16(sb + 2 * TILEB + sw, b0);
            cp16(sb + 3 * TILEB + sw, b1);
        }
        asm volatile("cp.async.commit_group;" ::: "memory");
    };

    const int wm = wid >> 1;
    const int wn = wid & 1;
    const int mbase = wm * 32;
    const int nbase = wn * 64;

    const int tle = lane >> 3;
    const int rin = lane & 7;
    const int a_moff = rin + (tle & 1) * 8;
    const int a_koff = (tle >> 1) * 16;
    const int b_noff = (tle < 2) ? rin : (rin + 8);
    const int b_koff = (tle & 1) * 16;

    float acc[2][8][4];
    #pragma unroll
    for (int i = 0; i < 2; i++)
        #pragma unroll
        for (int j = 0; j < 8; j++)
            #pragma unroll
            for (int k = 0; k < 4; k++) acc[i][j][k] = 0.f;

    auto compute_stage = [&](int buf) {
        const uint32_t sb = base + buf * STAGEB;
        #pragma unroll
        for (int ks = 0; ks < 2; ks++) {
            uint32_t ah[2][4], al[2][4], bh[4][4], bl[4][4];
            #pragma unroll
            for (int i = 0; i < 2; i++) {
                const uint32_t off = SWZ64((uint32_t)((mbase + 16 * i + a_moff) * 64 + ks * 32 + a_koff));
                ldsm_x4(ah[i], sb + 0 * TILEB + off);
                ldsm_x4(al[i], sb + 1 * TILEB + off);
            }
            #pragma unroll
            for (int jp = 0; jp < 4; jp++) {
                const uint32_t off = SWZ64((uint32_t)((nbase + 16 * jp + b_noff) * 64 + ks * 32 + b_koff));
                ldsm_x4(bh[jp], sb + 2 * TILEB + off);
                ldsm_x4(bl[jp], sb + 3 * TILEB + off);
            }
            #pragma unroll
            for (int i = 0; i < 2; i++) {
                #pragma unroll
                for (int j = 0; j < 8; j++)
                    mma16816(acc[i][j], ah[i], &bh[j >> 1][(j & 1) * 2]);
                #pragma unroll
                for (int j = 0; j < 8; j++)
                    mma16816(acc[i][j], ah[i], &bl[j >> 1][(j & 1) * 2]);
                #pragma unroll
                for (int j = 0; j < 8; j++)
                    mma16816(acc[i][j], al[i], &bh[j >> 1][(j & 1) * 2]);
            }
        }
    };

    load_stage(0, 0);
    for (int c = 0; c < NCHUNK; c++) {
        const int buf = c & 1;
        if (c + 1 < NCHUNK) {
            load_stage(c + 1, buf ^ 1);
            asm volatile("cp.async.wait_group 1;" ::: "memory");
        } else {
            asm volatile("cp.async.wait_group 0;" ::: "memory");
        }
        __syncthreads();
        compute_stage(buf);
        __syncthreads();
    }

    // Epilogue: stage 64 rows into smem (stride 132), then mode-specific writes
    const int lr = lane >> 2;
    const int lc = (lane & 3) * 2;
    for (int p = 0; p < 2; p++) {
        if ((wm >> 1) == p) {
            const int rb = mbase - p * 64;
            #pragma unroll
            for (int i = 0; i < 2; i++) {
                #pragma unroll
                for (int j = 0; j < 8; j++) {
                    const int rr = rb + 16 * i + lr;
                    const int cc = nbase + 8 * j + lc;
                    *(float2*)&stg[rr * 132 + cc]       = make_float2(acc[i][j][0], acc[i][j][1]);
                    *(float2*)&stg[(rr + 8) * 132 + cc] = make_float2(acc[i][j][2], acc[i][j][3]);
                }
            }
        }
        __syncthreads();
        if (MODE == MODE_V) {
            // transposed write: Vt[z][s][r]
            const int c = t >> 1;               // 0..127 column within tile
            const int rseg = (t & 1) * 32;      // rows of this 64-row half
            const int b = m0 >> 10;
            const int h = (n0 + c) >> 6, sO = (n0 + c) & 63;
            const int rglob0 = (m0 & 1023) + 64 * p + rseg;
            const size_t vo = (((size_t)(b * NH + h)) * NS + sO) * NR + rglob0;
            #pragma unroll 8
            for (int rl = 0; rl < 32; rl += 2) {
                store_split2(&g_VtH[vo + rl], &g_VtL[vo + rl],
                             stg[(rseg + rl) * 132 + c], stg[(rseg + rl + 1) * 132 + c]);
            }
        } else {
            const int rl = t >> 2;
            const int quad = t & 3;
            const int grow = m0 + 64 * p + rl;
            const int cq = quad * 32;
            const float* sp = stg + rl * 132 + cq;
            if (MODE == MODE_Q) {
                const int b = grow >> 9, q = grow & 511;
                const int h = (n0 + cq) >> 6, sO = (n0 + cq) & 63;
                const size_t o = (((size_t)(b * NH + h)) * NQ + q) * NS + sO;
                const float* cbp = cb + n0 + cq;
                const float* pbp = pb + n0 + cq;
                #pragma unroll
                for (int j = 0; j < 32; j += 2) {
                    const float v0 = sp[j], v1 = sp[j + 1];
                    store_split2(&g_QCh[o + j], &g_QCl[o + j], v0 + cbp[j], v1 + cbp[j + 1]);
                    store_split2(&g_QPh[o + j], &g_QPl[o + j], v0 + pbp[j], v1 + pbp[j + 1]);
                }
            } else if (MODE == MODE_KC) {
                const int b = grow >> 10, r = grow & 1023;
                const int h = (n0 + cq) >> 6, sO = (n0 + cq) & 63;
                const size_t o = (((size_t)(b * NH + h)) * NR + r) * NS + sO;
                #pragma unroll
                for (int j = 0; j < 32; j += 2)
                    store_split2(&g_KCh[o + j], &g_KCl[o + j], sp[j], sp[j + 1]);
            } else if (MODE == MODE_KP) {
                const int h = (n0 + cq) >> 6, sO = (n0 + cq) & 63;
                const size_t o = ((size_t)h * NR + grow) * NS + sO;
                #pragma unroll
                for (int j = 0; j < 32; j += 2)
                    store_split2(&g_KPh[o + j], &g_KPl[o + j], sp[j], sp[j + 1]);
            } else {  // MODE_OUT: final fp32 output
                float* d1 = outp + (size_t)grow * ND + n0 + cq;
                #pragma unroll
                for (int j = 0; j < 32; j += 4)
                    *(float4*)(d1 + j) = make_float4(sp[j], sp[j+1], sp[j+2], sp[j+3]);
            }
        }
        __syncthreads();
    }
}

// ---------------------------------------------------------------------------
// score_mma<PPMODE>: logits tile [64q x 64r] fp32 via split-bf16 mma, K=64.
// 128 threads = 4 warps (2m x 2n), warp tile 32x32. SW128 swizzle, 128B rows.
// ---------------------------------------------------------------------------
constexpr int STILE = 64 * 128;   // 8192 B per 64x64 bf16 tile

template <int PPMODE>
__global__ __launch_bounds__(128)
void score_mma()
{
    const int z  = blockIdx.z;
    const int q0 = blockIdx.y * 64;
    const int r0 = blockIdx.x * 64;
    if (PPMODE == 0) {
        if (r0 >= q0 + 576) return;
    } else {
        if (r0 + 63 < 448 - q0) return;
    }

    __shared__ char ssm[4 * STILE + 128];
    const uint32_t base = (smem_u32(ssm) + 127u) & ~127u;

    const int t = threadIdx.x;
    const int wid = t >> 5, lane = t & 31;

    const __nv_bfloat16* Ah = (PPMODE ? g_QPh : g_QCh) + ((size_t)z * NQ + q0) * NS;
    const __nv_bfloat16* Al = (PPMODE ? g_QPl : g_QCl) + ((size_t)z * NQ + q0) * NS;
    const __nv_bfloat16* Bh = PPMODE ? g_KPh + ((size_t)(z & 15) * NR + r0) * NS
                                     : g_KCh + ((size_t)z * NR + r0) * NS;
    const __nv_bfloat16* Bl = PPMODE ? g_KPl + ((size_t)(z & 15) * NR + r0) * NS
                                     : g_KCl + ((size_t)z * NR + r0) * NS;

    #pragma unroll
    for (int i = 0; i < 4; i++) {
        const int idx = t + 128 * i;
        const int row = idx >> 3, c16 = idx & 7;
        const uint32_t sw = SWZ128((uint32_t)(row * 128 + c16 * 16));
        const size_t go = (size_t)row * NS * 2 + c16 * 16;  // bytes
        cp16(base + 0 * STILE + sw, (const char*)Ah + go);
        cp16(base + 1 * STILE + sw, (const char*)Al + go);
        cp16(base + 2 * STILE + sw, (const char*)Bh + go);
        cp16(base + 3 * STILE + sw, (const char*)Bl + go);
    }
    asm volatile("cp.async.commit_group;" ::: "memory");
    asm volatile("cp.async.wait_group 0;" ::: "memory");
    __syncthreads();

    const int mbase = (wid >> 1) * 32;
    const int nbase = (wid & 1) * 32;
    const int tle = lane >> 3;
    const int rin = lane & 7;
    const int a_moff = rin + (tle & 1) * 8;
    const int a_koff = (tle >> 1) * 16;
    const int b_noff = (tle < 2) ? rin : (rin + 8);
    const int b_koff = (tle & 1) * 16;

    float acc[2][4][4];
    #pragma unroll
    for (int i = 0; i < 2; i++)
        #pragma unroll
        for (int j = 0; j < 4; j++)
            #pragma unroll
            for (int k = 0; k < 4; k++) acc[i][j][k] = 0.f;

    #pragma unroll
    for (int ks = 0; ks < 4; ks++) {
        uint32_t ah[2][4], al[2][4], bh[2][4], bl[2][4];
        #pragma unroll
        for (int i = 0; i < 2; i++) {
            const uint32_t off = SWZ128((uint32_t)((mbase + 16 * i + a_moff) * 128 + ks * 32 + a_koff));
            ldsm_x4(ah[i], base + 0 * STILE + off);
            ldsm_x4(al[i], base + 1 * STILE + off);
        }
        #pragma unroll
        for (int jp = 0; jp < 2; jp++) {
            const uint32_t off = SWZ128((uint32_t)((nbase + 16 * jp + b_noff) * 128 + ks * 32 + b_koff));
            ldsm_x4(bh[jp], base + 2 * STILE + off);
            ldsm_x4(bl[jp], base + 3 * STILE + off);
        }
        #pragma unroll
        for (int i = 0; i < 2; i++) {
            #pragma unroll
            for (int j = 0; j < 4; j++)
                mma16816(acc[i][j], ah[i], &bh[j >> 1][(j & 1) * 2]);
            #pragma unroll
            for (int j = 0; j < 4; j++)
                mma16816(acc[i][j], ah[i], &bl[j >> 1][(j & 1) * 2]);
            #pragma unroll
            for (int j = 0; j < 4; j++)
                mma16816(acc[i][j], al[i], &bh[j >> 1][(j & 1) * 2]);
        }
    }

    float* C = (PPMODE ? g_PP : g_CT) + (size_t)z * NQ * NR;
    const int r_ = lane >> 2;
    const int c2 = (lane & 3) * 2;
    #pragma unroll
    for (int i = 0; i < 2; i++) {
        #pragma unroll
        for (int j = 0; j < 4; j++) {
            const int row = q0 + mbase + 16 * i + r_;
            const int col = r0 + nbase + 8 * j + c2;
            *(float2*)&C[(size_t)row * NR + col]       = make_float2(acc[i][j][0], acc[i][j][1]);
            *(float2*)&C[(size_t)(row + 8) * NR + col] = make_float2(acc[i][j][2], acc[i][j][3]);
        }
    }
}

// ---------------------------------------------------------------------------
// Softmax with fused rel-shift gather; writes bf16-split probs up to the
// per-tile causal bound (q&~63)+576 (zeros past rv).
// ---------------------------------------------------------------------------
__global__ __launch_bounds__(256)
void softmax_kernel()
{
    const int q = blockIdx.x;
    const int z = blockIdx.y;
    const float* ct = g_CT + ((size_t)z * NQ + q) * NR;
    const float* pp = g_PP + ((size_t)z * NQ + q) * NR;
    const size_t po = ((size_t)z * NQ + q) * NR;
    const int rv = q + NM + 1;
    const int koff = NQ - 1 - q;
    const int bound = (q & ~63) + 576;

    __shared__ float sbuf[NR];
    __shared__ float redm[8], reds[8];
    const int t = threadIdx.x;
    const int lane = t & 31, warp = t >> 5;

    float m = -1e30f;
    for (int r = t; r < rv; r += 256) {
        const float v = (ct[r] + pp[r + koff]) * 0.125f;
        sbuf[r] = v;
        m = fmaxf(m, v);
    }
    #pragma unroll
    for (int o = 16; o; o >>= 1) m = fmaxf(m, __shfl_xor_sync(0xffffffffu, m, o));
    if (lane == 0) redm[warp] = m;
    __syncthreads();
    float mm = redm[0];
    #pragma unroll
    for (int w = 1; w < 8; w++) mm = fmaxf(mm, redm[w]);

    float sum = 0.f;
    for (int r = t; r < rv; r += 256) {
        const float e = expf(sbuf[r] - mm);
        sbuf[r] = e;
        sum += e;
    }
    #pragma unroll
    for (int o = 16; o; o >>= 1) sum += __shfl_xor_sync(0xffffffffu, sum, o);
    if (lane == 0) reds[warp] = sum;
    __syncthreads();
    float tot = 0.f;
    #pragma unroll
    for (int w = 0; w < 8; w++) tot += reds[w];
    const float inv = 1.f / tot;

    for (int r = t; r < bound; r += 256) {
        const float p = (r < rv) ? sbuf[r] * inv : 0.f;
        const __nv_bfloat16 hh = __float2bfloat16(p);
        g_Ph[po + r] = hh;
        g_Pl[po + r] = __float2bfloat16(p - __bfloat162float(hh));
    }
}

// ---------------------------------------------------------------------------
// av_mma: O[64q x 64s] = P[q, r] * Vt[s, r]^T via split-bf16 mma (3-pass).
// K-loop over r in chunks of 64 up to q0+576, 2-stage cp.async.
// ---------------------------------------------------------------------------
constexpr int AVTILE  = 64 * 128;       // 8192 B
constexpr int AVSTAGE = 4 * AVTILE;     // 32768
constexpr int AVSMEM  = 2 * AVSTAGE + 128;

__global__ __launch_bounds__(128)
void av_mma()
{
    extern __shared__ char dsm2[];
    const uint32_t base = (smem_u32(dsm2) + 127u) & ~127u;

    const int q0 = blockIdx.x * 64;
    const int z  = blockIdx.y;
    const int b = z >> 4, h = z & 15;

    const __nv_bfloat16* Ph = g_Ph + ((size_t)z * NQ + q0) * NR;
    const __nv_bfloat16* Pl = g_Pl + ((size_t)z * NQ + q0) * NR;
    const __nv_bfloat16* Vh = g_VtH + (size_t)z * NS * NR;
    const __nv_bfloat16* Vl = g_VtL + (size_t)z * NS * NR;

    const int t = threadIdx.x;
    const int wid = t >> 5, lane = t & 31;
    const int nchunks = q0 / 64 + 9;

    auto load_stage = [&](int c, int buf) {
        const uint32_t sb = base + buf * AVSTAGE;
        const size_t kb = (size_t)c * 128;   // bytes into row (64 bf16)
        #pragma unroll
        for (int i = 0; i < 4; i++) {
            const int idx = t + 128 * i;
            const int row = idx >> 3, c16 = idx & 7;
            const uint32_t sw = SWZ128((uint32_t)(row * 128 + c16 * 16));
            const size_t go = (size_t)row * NR * 2 + kb + c16 * 16;
            cp16(sb + 0 * AVTILE + sw, (const char*)Ph + go);
            cp16(sb + 1 * AVTILE + sw, (const char*)Pl + go);
            cp16(sb + 2 * AVTILE + sw, (const char*)Vh + go);
            cp16(sb + 3 * AVTILE + sw, (const char*)Vl + go);
        }
        asm volatile("cp.async.commit_group;" ::: "memory");
    };

    const int mbase = (wid >> 1) * 32;
    const int nbase = (wid & 1) * 32;
    const int tle = lane >> 3;
    const int rin = lane & 7;
    const int a_moff = rin + (tle & 1) * 8;
    const int a_koff = (tle >> 1) * 16;
    const int b_noff = (tle < 2) ? rin : (rin + 8);
    const int b_koff = (tle & 1) * 16;

    float acc[2][4][4];
    #pragma unroll
    for (int i = 0; i < 2; i++)
        #pragma unroll
        for (int j = 0; j < 4; j++)
            #pragma unroll
            for (int k = 0; k < 4; k++) acc[i][j][k] = 0.f;

    auto compute_stage = [&](int buf) {
        const uint32_t sb = base + buf * AVSTAGE;
        #pragma unroll
        for (int ks = 0; ks < 4; ks++) {
            uint32_t ah[2][4], al[2][4], bh[2][4], bl[2][4];
            #pragma unroll
            for (int i = 0; i < 2; i++) {
                const uint32_t off = SWZ128((uint32_t)((mbase + 16 * i + a_moff) * 128 + ks * 32 + a_koff));
                ldsm_x4(ah[i], sb + 0 * AVTILE + off);
                ldsm_x4(al[i], sb + 1 * AVTILE + off);
            }
            #pragma unroll
            for (int jp = 0; jp < 2; jp++) {
                const uint32_t off = SWZ128((uint32_t)((nbase + 16 * jp + b_noff) * 128 + ks * 32 + b_koff));
                ldsm_x4(bh[jp], sb + 2 * AVTILE + off);
                ldsm_x4(bl[jp], sb + 3 * AVTILE + off);
            }
            #pragma unroll
            for (int i = 0; i < 2; i++) {
                #pragma unroll
                for (int j = 0; j < 4; j++)
                    mma16816(acc[i][j], ah[i], &bh[j >> 1][(j & 1) * 2]);
                #pragma unroll
                for (int j = 0; j < 4; j++)
                    mma16816(acc[i][j], ah[i], &bl[j >> 1][(j & 1) * 2]);
                #pragma unroll
                for (int j = 0; j < 4; j++)
                    mma16816(acc[i][j], al[i], &bh[j >> 1][(j & 1) * 2]);
            }
        }
    };

    load_stage(0, 0);
    for (int c = 0; c < nchunks; c++) {
        const int buf = c & 1;
        if (c + 1 < nchunks) {
            load_stage(c + 1, buf ^ 1);
            asm volatile("cp.async.wait_group 1;" ::: "memory");
        } else {
            asm volatile("cp.async.wait_group 0;" ::: "memory");
        }
        __syncthreads();
        compute_stage(buf);
        __syncthreads();
    }

    // Epilogue: split fp32 accums to bf16 hi/lo, write [b,q][h*64+s]
    const int r_ = lane >> 2;
    const int c2 = (lane & 3) * 2;
    #pragma unroll
    for (int i = 0; i < 2; i++) {
        #pragma unroll
        for (int j = 0; j < 4; j++) {
            const int q = q0 + mbase + 16 * i + r_;
            const int col = h * 64 + nbase + 8 * j + c2;
            const size_t o1 = ((size_t)(b * NQ + q)) * ND + col;
            const size_t o2 = ((size_t)(b * NQ + q + 8)) * ND + col;
            store_split2(&g_OH[o1], &g_OL[o1], acc[i][j][0], acc[i][j][1]);
            store_split2(&g_OH[o2], &g_OL[o2], acc[i][j][2], acc[i][j][3]);
        }
    }
}

// ---------------------------------------------------------------------------
extern "C" void kernel_launch(void* const* d_in, const int* in_sizes, int n_in,
                              void* d_out, int out_size)
{
    const float* qry = (const float*)d_in[0];
    const float* mem = (const float*)d_in[1];
    const float* pe  = (const float*)d_in[2];
    const float* cb  = (const float*)d_in[4];
    const float* pb  = (const float*)d_in[5];
    const float* Wq  = (const float*)d_in[6];
    const float* Wkc = (const float*)d_in[7];
    const float* Wkp = (const float*)d_in[8];
    const float* Wv  = (const float*)d_in[9];
    const float* Wo  = (const float*)d_in[10];
    float* out = (float*)d_out;

    cudaFuncSetAttribute(mma_gemm<MODE_Q>,   cudaFuncAttributeMaxDynamicSharedMemorySize, GSMEM);
    cudaFuncSetAttribute(mma_gemm<MODE_KC>,  cudaFuncAttributeMaxDynamicSharedMemorySize, GSMEM);
    cudaFuncSetAttribute(mma_gemm<MODE_V>,   cudaFuncAttributeMaxDynamicSharedMemorySize, GSMEM);
    cudaFuncSetAttribute(mma_gemm<MODE_KP>,  cudaFuncAttributeMaxDynamicSharedMemorySize, GSMEM);
    cudaFuncSetAttribute(mma_gemm<MODE_OUT>, cudaFuncAttributeMaxDynamicSharedMemorySize, GSMEM);
    cudaFuncSetAttribute(av_mma, cudaFuncAttributeMaxDynamicSharedMemorySize, AVSMEM);

    dim3 thr(256);
    dim3 wtb(32, 8);

    // conversions
    conv_xref<<<NB * NR, 256>>>(qry, mem);
    conv_pe<<<(NR * ND) / 256, 256>>>(pe);
    conv_wt<0><<<dim3(32, 32), wtb>>>(Wq);
    conv_wt<1><<<dim3(32, 32), wtb>>>(Wkc);
    conv_wt<2><<<dim3(32, 32), wtb>>>(Wkp);
    conv_wt<3><<<dim3(32, 32), wtb>>>(Wv);
    conv_wt<4><<<dim3(32, 32), wtb>>>(Wo);

    // projections (split bf16 mma.sync) -> bf16-split attention operands
    mma_gemm<MODE_Q ><<<dim3(8, 32), thr, GSMEM>>>(cb, pb, nullptr);
    mma_gemm<MODE_KC><<<dim3(8, 64), thr, GSMEM>>>(nullptr, nullptr, nullptr);
    mma_gemm<MODE_V ><<<dim3(8, 64), thr, GSMEM>>>(nullptr, nullptr, nullptr);
    mma_gemm<MODE_KP><<<dim3(8, 8),  thr, GSMEM>>>(nullptr, nullptr, nullptr);

    // attention core (split bf16 mma.sync)
    score_mma<0><<<dim3(16, 8, NB * NH), 128>>>();
    score_mma<1><<<dim3(16, 8, NB * NH), 128>>>();
    softmax_kernel<<<dim3(NQ, NB * NH), thr>>>();
    av_mma<<<dim3(8, NB * NH), 128, AVSMEM>>>();

    // output projection
    mma_gemm<MODE_OUT><<<dim3(8, 32), thr, GSMEM>>>(nullptr, nullptr, out);
}

// round 9
// speedup vs baseline: 4.5108x; 1.1330x over previous
#include <cuda_runtime.h>
#include <cuda_bf16.h>
#include <math.h>
#include <stdint.h>

// Problem constants
constexpr int NB = 8;     // batch
constexpr int NQ = 512;   // query len
constexpr int NM = 512;   // memory len
constexpr int NR = 1024;  // reference len
constexpr int NH = 16;    // heads
constexpr int NS = 64;    // size per head
constexpr int ND = 1024;  // hidden

#define ALGN __align__(16)

// bf16 split attention operands (written by projection epilogues)
__device__ ALGN __nv_bfloat16 g_QCh[(size_t)NB*NH*NQ*NS];
__device__ ALGN __nv_bfloat16 g_QCl[(size_t)NB*NH*NQ*NS];
__device__ ALGN __nv_bfloat16 g_QPh[(size_t)NB*NH*NQ*NS];
__device__ ALGN __nv_bfloat16 g_QPl[(size_t)NB*NH*NQ*NS];
__device__ ALGN __nv_bfloat16 g_KCh[(size_t)NB*NH*NR*NS];
__device__ ALGN __nv_bfloat16 g_KCl[(size_t)NB*NH*NR*NS];
__device__ ALGN __nv_bfloat16 g_KPh[(size_t)NH*NR*NS];
__device__ ALGN __nv_bfloat16 g_KPl[(size_t)NH*NR*NS];
__device__ ALGN __nv_bfloat16 g_VtH[(size_t)NB*NH*NS*NR];  // V transposed [z][s][r]
__device__ ALGN __nv_bfloat16 g_VtL[(size_t)NB*NH*NS*NR];
// attention output (bf16 split, written by fused_attn)
__device__ ALGN __nv_bfloat16 g_OH[(size_t)NB*NQ*ND];
__device__ ALGN __nv_bfloat16 g_OL[(size_t)NB*NQ*ND];

// bf16 split inputs for projections
__device__ ALGN __nv_bfloat16 g_XrefH[(size_t)NB*NR*ND];
__device__ ALGN __nv_bfloat16 g_XrefL[(size_t)NB*NR*ND];
__device__ ALGN __nv_bfloat16 g_PEH[(size_t)NR*ND];
__device__ ALGN __nv_bfloat16 g_PEL[(size_t)NR*ND];
// transposed weights Wt[c][k]: 0=Wq 1=Wkc 2=Wkp 3=Wv 4=Wo
__device__ ALGN __nv_bfloat16 g_WtH[5][(size_t)ND*ND];
__device__ ALGN __nv_bfloat16 g_WtL[5][(size_t)ND*ND];

enum { MODE_Q = 0, MODE_KC = 1, MODE_V = 2, MODE_KP = 3, MODE_OUT = 4 };

// ---------------------------------------------------------------------------
// helpers
// ---------------------------------------------------------------------------
__device__ __forceinline__ uint32_t smem_u32(const void* p) {
    uint32_t a;
    asm("{ .reg .u64 t; cvta.to.shared.u64 t, %1; cvt.u32.u64 %0, t; }"
        : "=r"(a) : "l"(p));
    return a;
}
__device__ __forceinline__ void cp16(uint32_t dst, const void* src) {
    asm volatile("cp.async.cg.shared.global [%0], [%1], 16;"
                 :: "r"(dst), "l"(src) : "memory");
}
__device__ __forceinline__ void ldsm_x4(uint32_t* r, uint32_t addr) {
    asm volatile("ldmatrix.sync.aligned.m8n8.x4.shared.b16 {%0,%1,%2,%3}, [%4];"
                 : "=r"(r[0]), "=r"(r[1]), "=r"(r[2]), "=r"(r[3]) : "r"(addr));
}
__device__ __forceinline__ void mma16816(float* c, const uint32_t* a, const uint32_t* b) {
    asm volatile(
        "mma.sync.aligned.m16n8k16.row.col.f32.bf16.bf16.f32 "
        "{%0,%1,%2,%3}, {%4,%5,%6,%7}, {%8,%9}, {%0,%1,%2,%3};"
        : "+f"(c[0]), "+f"(c[1]), "+f"(c[2]), "+f"(c[3])
        : "r"(a[0]), "r"(a[1]), "r"(a[2]), "r"(a[3]), "r"(b[0]), "r"(b[1]));
}
#define SWZ64(x)  ((x) ^ (((x) >> 3) & 0x30))
#define SWZ128(x) ((x) ^ (((x) >> 3) & 0x70))

__device__ __forceinline__ void split1(float v, __nv_bfloat16& h, __nv_bfloat16& l) {
    h = __float2bfloat16(v);
    l = __float2bfloat16(v - __bfloat162float(h));
}
__device__ __forceinline__ void store_split2(__nv_bfloat16* ph, __nv_bfloat16* pl,
                                             float a, float b) {
    __nv_bfloat162 hh, ll;
    hh.x = __float2bfloat16(a);
    ll.x = __float2bfloat16(a - __bfloat162float(hh.x));
    hh.y = __float2bfloat16(b);
    ll.y = __float2bfloat16(b - __bfloat162float(hh.y));
    *(__nv_bfloat162*)ph = hh;
    *(__nv_bfloat162*)pl = ll;
}
__device__ __forceinline__ uint32_t pack_split(float a, float b, uint32_t& lo) {
    __nv_bfloat162 hh, ll;
    hh.x = __float2bfloat16(a);
    ll.x = __float2bfloat16(a - __bfloat162float(hh.x));
    hh.y = __float2bfloat16(b);
    ll.y = __float2bfloat16(b - __bfloat162float(hh.y));
    lo = *(uint32_t*)&ll;
    return *(uint32_t*)&hh;
}

// ---------------------------------------------------------------------------
// Conversion kernels
// ---------------------------------------------------------------------------
__global__ void conv_xref(const float* __restrict__ qry, const float* __restrict__ mem) {
    const int row = blockIdx.x;
    const int b = row >> 10, r = row & 1023;
    const float* src = (r < NM) ? mem + ((size_t)(b * NM + r)) * ND
                                : qry + ((size_t)(b * NQ + (r - NM))) * ND;
    const int c = threadIdx.x * 4;
    float4 v = *(const float4*)(src + c);
    const size_t o = (size_t)row * ND + c;
    split1(v.x, g_XrefH[o+0], g_XrefL[o+0]);
    split1(v.y, g_XrefH[o+1], g_XrefL[o+1]);
    split1(v.z, g_XrefH[o+2], g_XrefL[o+2]);
    split1(v.w, g_XrefH[o+3], g_XrefL[o+3]);
}

__global__ void conv_pe(const float* __restrict__ src) {
    const size_t i = (size_t)blockIdx.x * blockDim.x + threadIdx.x;
    split1(src[i], g_PEH[i], g_PEL[i]);
}

template <int WID>
__global__ void conv_wt(const float* __restrict__ W) {
    __shared__ float tile[32][33];
    const int c0 = blockIdx.x * 32, k0 = blockIdx.y * 32;
    const int tx = threadIdx.x, ty = threadIdx.y;  // 32 x 8
    for (int i = ty; i < 32; i += 8)
        tile[i][tx] = W[(size_t)(k0 + i) * ND + c0 + tx];
    __syncthreads();
    for (int i = ty; i < 32; i += 8) {
        float v = tile[tx][i];
        __nv_bfloat16 h, l;
        split1(v, h, l);
        const size_t o = (size_t)(c0 + i) * ND + k0 + tx;
        g_WtH[WID][o] = h;
        g_WtL[WID][o] = l;
    }
}

// ---------------------------------------------------------------------------
// Split-bf16 mma.sync projection GEMM (3-pass) — unchanged (passing R7).
// ---------------------------------------------------------------------------
constexpr int TILEB  = 128 * 64;
constexpr int STAGEB = 4 * TILEB;
constexpr int GSMEM  = 2 * STAGEB + 1024;
constexpr int NCHUNK = ND / 32;

template <int MODE>
__global__ __launch_bounds__(256)
void mma_gemm(const float* __restrict__ cb, const float* __restrict__ pb,
              float* __restrict__ outp)
{
    extern __shared__ char dsm[];
    const uint32_t dyn_u32 = smem_u32(dsm);
    const uint32_t base = (dyn_u32 + 1023u) & ~1023u;
    float* stg = reinterpret_cast<float*>(dsm + (base - dyn_u32));

    const int t = threadIdx.x;
    const int wid = t >> 5, lane = t & 31;
    const int n0 = blockIdx.x * 128;
    const int m0 = blockIdx.y * 128;
    const int arow0 = (MODE == MODE_Q) ? ((m0 >> 9) * 1024 + 512 + (m0 & 511)) : m0;

    const __nv_bfloat16 *Ah, *Al, *Bh, *Bl;
    if (MODE == MODE_Q)       { Ah = g_XrefH; Al = g_XrefL; Bh = g_WtH[0]; Bl = g_WtL[0]; }
    else if (MODE == MODE_KC) { Ah = g_XrefH; Al = g_XrefL; Bh = g_WtH[1]; Bl = g_WtL[1]; }
    else if (MODE == MODE_KP) { Ah = g_PEH;   Al = g_PEL;   Bh = g_WtH[2]; Bl = g_WtL[2]; }
    else if (MODE == MODE_V)  { Ah = g_XrefH; Al = g_XrefL; Bh = g_WtH[3]; Bl = g_WtL[3]; }
    else                      { Ah = g_OH;    Al = g_OL;    Bh = g_WtH[4]; Bl = g_WtL[4]; }

    const int s0 = t;
    const int mseg0 = s0 >> 2, cseg0 = s0 & 3;
    const int s1 = t + 256;
    const int mseg1 = s1 >> 2, cseg1 = s1 & 3;

    auto load_stage = [&](int chunk, int buf) {
        const uint32_t sb = base + buf * STAGEB;
        const int kbyte = chunk * 64;
        {
            const char* a0 = (const char*)(Ah + (size_t)(arow0 + mseg0) * ND) + kbyte + cseg0 * 16;
            const char* a1 = (const char*)(Al + (size_t)(arow0 + mseg0) * ND) + kbyte + cseg0 * 16;
            const char* b0 = (const char*)(Bh + (size_t)(n0 + mseg0) * ND) + kbyte + cseg0 * 16;
            const char* b1 = (const char*)(Bl + (size_t)(n0 + mseg0) * ND) + kbyte + cseg0 * 16;
            const uint32_t sw = SWZ64((uint32_t)(mseg0 * 64 + cseg0 * 16));
            cp16(sb + 0 * TILEB + sw, a0);
            cp16(sb + 1 * TILEB + sw, a1);
            cp16(sb + 2 * TILEB + sw, b0);
            cp16(sb + 3 * TILEB + sw, b1);
        }
        {
            const char* a0 = (const char*)(Ah + (size_t)(arow0 + mseg1) * ND) + kbyte + cseg1 * 16;
            const char* a1 = (const char*)(Al + (size_t)(arow0 + mseg1) * ND) + kbyte + cseg1 * 16;
            const char* b0 = (const char*)(Bh + (size_t)(n0 + mseg1) * ND) + kbyte + cseg1 * 16;
            const char* b1 = (const char*)(Bl + (size_t)(n0 + mseg1) * ND) + kbyte + cseg1 * 16;
            const uint32_t sw = SWZ64((uint32_t)(mseg1 * 64 + cseg1 * 16));
            cp16(sb + 0 * TILEB + sw, a0);
            cp16(sb + 1 * TILEB + sw, a1);
            cp16(sb + 2 * TILEB + sw, b0);
            cp16(sb + 3 * TILEB + sw, b1);
        }
        asm volatile("cp.async.commit_group;" ::: "memory");
    };

    const int wm = wid >> 1;
    const int wn = wid & 1;
    const int mbase = wm * 32;
    const int nbase = wn * 64;

    const int tle = lane >> 3;
    const int rin = lane & 7;
    const int a_moff = rin + (tle & 1) * 8;
    const int a_koff = (tle >> 1) * 16;
    const int b_noff = (tle < 2) ? rin : (rin + 8);
    const int b_koff = (tle & 1) * 16;

    float acc[2][8][4];
    #pragma unroll
    for (int i = 0; i < 2; i++)
        #pragma unroll
        for (int j = 0; j < 8; j++)
            #pragma unroll
            for (int k = 0; k < 4; k++) acc[i][j][k] = 0.f;

    auto compute_stage = [&](int buf) {
        const uint32_t sb = base + buf * STAGEB;
        #pragma unroll
        for (int ks = 0; ks < 2; ks++) {
            uint32_t ah[2][4], al[2][4], bh[4][4], bl[4][4];
            #pragma unroll
            for (int i = 0; i < 2; i++) {
                const uint32_t off = SWZ64((uint32_t)((mbase + 16 * i + a_moff) * 64 + ks * 32 + a_koff));
                ldsm_x4(ah[i], sb + 0 * TILEB + off);
                ldsm_x4(al[i], sb + 1 * TILEB + off);
            }
            #pragma unroll
            for (int jp = 0; jp < 4; jp++) {
                const uint32_t off = SWZ64((uint32_t)((nbase + 16 * jp + b_noff) * 64 + ks * 32 + b_koff));
                ldsm_x4(bh[jp], sb + 2 * TILEB + off);
                ldsm_x4(bl[jp], sb + 3 * TILEB + off);
            }
            #pragma unroll
            for (int i = 0; i < 2; i++) {
                #pragma unroll
                for (int j = 0; j < 8; j++)
                    mma16816(acc[i][j], ah[i], &bh[j >> 1][(j & 1) * 2]);
                #pragma unroll
                for (int j = 0; j < 8; j++)
                    mma16816(acc[i][j], ah[i], &bl[j >> 1][(j & 1) * 2]);
                #pragma unroll
                for (int j = 0; j < 8; j++)
                    mma16816(acc[i][j], al[i], &bh[j >> 1][(j & 1) * 2]);
            }
        }
    };

    load_stage(0, 0);
    for (int c = 0; c < NCHUNK; c++) {
        const int buf = c & 1;
        if (c + 1 < NCHUNK) {
            load_stage(c + 1, buf ^ 1);
            asm volatile("cp.async.wait_group 1;" ::: "memory");
        } else {
            asm volatile("cp.async.wait_group 0;" ::: "memory");
        }
        __syncthreads();
        compute_stage(buf);
        __syncthreads();
    }

    const int lr = lane >> 2;
    const int lc = (lane & 3) * 2;
    for (int p = 0; p < 2; p++) {
        if ((wm >> 1) == p) {
            const int rb = mbase - p * 64;
            #pragma unroll
            for (int i = 0; i < 2; i++) {
                #pragma unroll
                for (int j = 0; j < 8; j++) {
                    const int rr = rb + 16 * i + lr;
                    const int cc = nbase + 8 * j + lc;
                    *(float2*)&stg[rr * 132 + cc]       = make_float2(acc[i][j][0], acc[i][j][1]);
                    *(float2*)&stg[(rr + 8) * 132 + cc] = make_float2(acc[i][j][2], acc[i][j][3]);
                }
            }
        }
        __syncthreads();
        if (MODE == MODE_V) {
            const int c = t >> 1;
            const int rseg = (t & 1) * 32;
            const int b = m0 >> 10;
            const int h = (n0 + c) >> 6, sO = (n0 + c) & 63;
            const int rglob0 = (m0 & 1023) + 64 * p + rseg;
            const size_t vo = (((size_t)(b * NH + h)) * NS + sO) * NR + rglob0;
            #pragma unroll 8
            for (int rl = 0; rl < 32; rl += 2) {
                store_split2(&g_VtH[vo + rl], &g_VtL[vo + rl],
                             stg[(rseg + rl) * 132 + c], stg[(rseg + rl + 1) * 132 + c]);
            }
        } else {
            const int rl = t >> 2;
            const int quad = t & 3;
            const int grow = m0 + 64 * p + rl;
            const int cq = quad * 32;
            const float* sp = stg + rl * 132 + cq;
            if (MODE == MODE_Q) {
                const int b = grow >> 9, q = grow & 511;
                const int h = (n0 + cq) >> 6, sO = (n0 + cq) & 63;
                const size_t o = (((size_t)(b * NH + h)) * NQ + q) * NS + sO;
                const float* cbp = cb + n0 + cq;
                const float* pbp = pb + n0 + cq;
                #pragma unroll
                for (int j = 0; j < 32; j += 2) {
                    const float v0 = sp[j], v1 = sp[j + 1];
                    store_split2(&g_QCh[o + j], &g_QCl[o + j], v0 + cbp[j], v1 + cbp[j + 1]);
                    store_split2(&g_QPh[o + j], &g_QPl[o + j], v0 + pbp[j], v1 + pbp[j + 1]);
                }
            } else if (MODE == MODE_KC) {
                const int b = grow >> 10, r = grow & 1023;
                const int h = (n0 + cq) >> 6, sO = (n0 + cq) & 63;
                const size_t o = (((size_t)(b * NH + h)) * NR + r) * NS + sO;
                #pragma unroll
                for (int j = 0; j < 32; j += 2)
                    store_split2(&g_KCh[o + j], &g_KCl[o + j], sp[j], sp[j + 1]);
            } else if (MODE == MODE_KP) {
                const int h = (n0 + cq) >> 6, sO = (n0 + cq) & 63;
                const size_t o = ((size_t)h * NR + grow) * NS + sO;
                #pragma unroll
                for (int j = 0; j < 32; j += 2)
                    store_split2(&g_KPh[o + j], &g_KPl[o + j], sp[j], sp[j + 1]);
            } else {
                float* d1 = outp + (size_t)grow * ND + n0 + cq;
                #pragma unroll
                for (int j = 0; j < 32; j += 4)
                    *(float4*)(d1 + j) = make_float4(sp[j], sp[j+1], sp[j+2], sp[j+3]);
            }
        }
        __syncthreads();
    }
}

// ---------------------------------------------------------------------------
// fused_attn: flash-attention style fused score + rel-shift + softmax + P*V.
// Grid (qt 0..7, z 0..127), 128 threads = 4 warps, warp owns 16 q-rows.
// ---------------------------------------------------------------------------
constexpr int F_T   = 8192;            // one 64x128B tile
constexpr int OFF_Q  = 0;              // QCh,QCl,QPh,QPl
constexpr int OFF_KC = 4 * F_T;        // 2 bufs x (h,l)
constexpr int OFF_V  = 8 * F_T;        // 2 bufs x (h,l)
constexpr int OFF_KP = 12 * F_T;       // 3 slots x (h,l)
constexpr int OFF_PP = 18 * F_T;       // 64 x 132 fp32
constexpr int PPS    = 132;
constexpr int FSMEM  = OFF_PP + 64 * PPS * 4 + 1024;

__global__ __launch_bounds__(128)
void fused_attn()
{
    extern __shared__ char fsm[];
    const uint32_t raw = smem_u32(fsm);
    const uint32_t base = (raw + 1023u) & ~1023u;
    float* sPP = reinterpret_cast<float*>(fsm + (base - raw) + OFF_PP);

    const int qt = blockIdx.x;
    const int z  = blockIdx.y;
    const int q0 = qt * 64;
    const int b = z >> 4, h = z & 15;
    const int nt = qt + 9;
    const int tj0 = 7 - qt;

    const int t = threadIdx.x;
    const int wid = t >> 5, lane = t & 31;
    const int mrow = wid * 16;

    const char* QCh = (const char*)(g_QCh + ((size_t)z * NQ + q0) * NS);
    const char* QCl = (const char*)(g_QCl + ((size_t)z * NQ + q0) * NS);
    const char* QPh = (const char*)(g_QPh + ((size_t)z * NQ + q0) * NS);
    const char* QPl = (const char*)(g_QPl + ((size_t)z * NQ + q0) * NS);
    const char* KCh = (const char*)(g_KCh + (size_t)z * NR * NS);
    const char* KCl = (const char*)(g_KCl + (size_t)z * NR * NS);
    const char* KPh = (const char*)(g_KPh + (size_t)h * NR * NS);
    const char* KPl = (const char*)(g_KPl + (size_t)h * NR * NS);
    const char* Vh  = (const char*)(g_VtH + (size_t)z * NS * NR);
    const char* Vl  = (const char*)(g_VtL + (size_t)z * NS * NR);

    auto load_kcv = [&](int c, int buf) {
        const uint32_t kb = base + OFF_KC + buf * 2 * F_T;
        const uint32_t vb = base + OFF_V  + buf * 2 * F_T;
        #pragma unroll
        for (int i = 0; i < 4; i++) {
            const int idx = t + 128 * i;
            const int row = idx >> 3, c16 = idx & 7;
            const uint32_t sw = SWZ128((uint32_t)(row * 128 + c16 * 16));
            const size_t kco = (size_t)(c * 64 + row) * 128 + c16 * 16;
            cp16(kb + sw,        KCh + kco);
            cp16(kb + F_T + sw,  KCl + kco);
            const size_t vo = (size_t)row * (NR * 2) + (size_t)c * 128 + c16 * 16;
            cp16(vb + sw,        Vh + vo);
            cp16(vb + F_T + sw,  Vl + vo);
        }
    };
    auto load_kp = [&](int tj) {
        const int slot = tj % 3;
        const uint32_t kb = base + OFF_KP + slot * 2 * F_T;
        #pragma unroll
        for (int i = 0; i < 4; i++) {
            const int idx = t + 128 * i;
            const int row = idx >> 3, c16 = idx & 7;
            int k = tj * 64 + row;
            if (k > 1023) k = 1023;               // clamped rows are masked later
            const uint32_t sw = SWZ128((uint32_t)(row * 128 + c16 * 16));
            cp16(kb + sw,       KPh + (size_t)k * 128 + c16 * 16);
            cp16(kb + F_T + sw, KPl + (size_t)k * 128 + c16 * 16);
        }
    };

    // prologue: Q tiles + first KC/V + first two KP tiles
    #pragma unroll
    for (int i = 0; i < 4; i++) {
        const int idx = t + 128 * i;
        const int row = idx >> 3, c16 = idx & 7;
        const uint32_t sw = SWZ128((uint32_t)(row * 128 + c16 * 16));
        const size_t qo = (size_t)row * 128 + c16 * 16;
        cp16(base + OFF_Q + 0 * F_T + sw, QCh + qo);
        cp16(base + OFF_Q + 1 * F_T + sw, QCl + qo);
        cp16(base + OFF_Q + 2 * F_T + sw, QPh + qo);
        cp16(base + OFF_Q + 3 * F_T + sw, QPl + qo);
    }
    load_kcv(0, 0);
    load_kp(tj0);
    load_kp(tj0 + 1);
    asm volatile("cp.async.commit_group;" ::: "memory");
    asm volatile("cp.async.wait_group 0;" ::: "memory");
    __syncthreads();

    const int tle = lane >> 3;
    const int rin = lane & 7;
    const int a_moff = rin + (tle & 1) * 8;
    const int a_koff = (tle >> 1) * 16;
    const int b_noff = (tle < 2) ? rin : (rin + 8);
    const int b_koff = (tle & 1) * 16;
    const int r_ = lane >> 2;
    const int c2 = (lane & 3) * 2;
    const int row0 = mrow + r_;
    const int row1 = row0 + 8;

    // preload Q a-frags (persistent)
    uint32_t qch[4][4], qcl[4][4], qph[4][4], qpl[4][4];
    #pragma unroll
    for (int ks = 0; ks < 4; ks++) {
        const uint32_t off = SWZ128((uint32_t)((mrow + a_moff) * 128 + ks * 32 + a_koff));
        ldsm_x4(qch[ks], base + OFF_Q + 0 * F_T + off);
        ldsm_x4(qcl[ks], base + OFF_Q + 1 * F_T + off);
        ldsm_x4(qph[ks], base + OFF_Q + 2 * F_T + off);
        ldsm_x4(qpl[ks], base + OFF_Q + 3 * F_T + off);
    }

    float m0 = -1e30f, m1 = -1e30f, s0 = 0.f, s1 = 0.f;
    float acc_o[8][4];
    #pragma unroll
    for (int j = 0; j < 8; j++)
        #pragma unroll
        for (int e = 0; e < 4; e++) acc_o[j][e] = 0.f;

    for (int c = 0; c < nt; c++) {
        const int buf = c & 1;
        if (c + 1 < nt) {
            load_kcv(c + 1, buf ^ 1);
            load_kp(tj0 + c + 2);
            asm volatile("cp.async.commit_group;" ::: "memory");
            asm volatile("cp.async.wait_group 1;" ::: "memory");
        } else {
            asm volatile("cp.async.wait_group 0;" ::: "memory");
        }
        __syncthreads();

        // --- content logits (3-pass, K=64) ---
        float cl[8][4];
        #pragma unroll
        for (int j = 0; j < 8; j++)
            #pragma unroll
            for (int e = 0; e < 4; e++) cl[j][e] = 0.f;
        {
            const uint32_t kb = base + OFF_KC + buf * 2 * F_T;
            #pragma unroll
            for (int ks = 0; ks < 4; ks++) {
                uint32_t bh[4][4], bl[4][4];
                #pragma unroll
                for (int jp = 0; jp < 4; jp++) {
                    const uint32_t off = SWZ128((uint32_t)((16 * jp + b_noff) * 128 + ks * 32 + b_koff));
                    ldsm_x4(bh[jp], kb + off);
                    ldsm_x4(bl[jp], kb + F_T + off);
                }
                #pragma unroll
                for (int j = 0; j < 8; j++)
                    mma16816(cl[j], qch[ks], &bh[j >> 1][(j & 1) * 2]);
                #pragma unroll
                for (int j = 0; j < 8; j++)
                    mma16816(cl[j], qch[ks], &bl[j >> 1][(j & 1) * 2]);
                #pragma unroll
                for (int j = 0; j < 8; j++)
                    mma16816(cl[j], qcl[ks], &bh[j >> 1][(j & 1) * 2]);
            }
        }

        // --- positional band (2 k-tiles) -> sPP ---
        #pragma unroll
        for (int half = 0; half < 2; half++) {
            const int slot = (tj0 + c + half) % 3;
            const uint32_t kb = base + OFF_KP + slot * 2 * F_T;
            float pa[8][4];
            #pragma unroll
            for (int j = 0; j < 8; j++)
                #pragma unroll
                for (int e = 0; e < 4; e++) pa[j][e] = 0.f;
            #pragma unroll
            for (int ks = 0; ks < 4; ks++) {
                uint32_t bh[4][4], bl[4][4];
                #pragma unroll
                for (int jp = 0; jp < 4; jp++) {
                    const uint32_t off = SWZ128((uint32_t)((16 * jp + b_noff) * 128 + ks * 32 + b_koff));
                    ldsm_x4(bh[jp], kb + off);
                    ldsm_x4(bl[jp], kb + F_T + off);
                }
                #pragma unroll
                for (int j = 0; j < 8; j++)
                    mma16816(pa[j], qph[ks], &bh[j >> 1][(j & 1) * 2]);
                #pragma unroll
                for (int j = 0; j < 8; j++)
                    mma16816(pa[j], qph[ks], &bl[j >> 1][(j & 1) * 2]);
                #pragma unroll
                for (int j = 0; j < 8; j++)
                    mma16816(pa[j], qpl[ks], &bh[j >> 1][(j & 1) * 2]);
            }
            #pragma unroll
            for (int j = 0; j < 8; j++) {
                const int col = half * 64 + 8 * j + c2;
                *(float2*)&sPP[row0 * PPS + col] = make_float2(pa[j][0], pa[j][1]);
                *(float2*)&sPP[row1 * PPS + col] = make_float2(pa[j][2], pa[j][3]);
            }
        }
        __syncthreads();

        // --- gather + mask + online softmax ---
        const bool last = (c == nt - 1);
        float rmax0 = -1e30f, rmax1 = -1e30f;
        #pragma unroll
        for (int j = 0; j < 8; j++) {
            const int rj = 8 * j + c2;
            float v0 = (cl[j][0] + sPP[row0 * PPS + rj     + 63 - row0]) * 0.125f;
            float v1 = (cl[j][1] + sPP[row0 * PPS + rj + 1 + 63 - row0]) * 0.125f;
            float v2 = (cl[j][2] + sPP[row1 * PPS + rj     + 63 - row1]) * 0.125f;
            float v3 = (cl[j][3] + sPP[row1 * PPS + rj + 1 + 63 - row1]) * 0.125f;
            if (last) {
                if (rj     > row0) v0 = -1e30f;
                if (rj + 1 > row0) v1 = -1e30f;
                if (rj     > row1) v2 = -1e30f;
                if (rj + 1 > row1) v3 = -1e30f;
            }
            cl[j][0] = v0; cl[j][1] = v1; cl[j][2] = v2; cl[j][3] = v3;
            rmax0 = fmaxf(rmax0, fmaxf(v0, v1));
            rmax1 = fmaxf(rmax1, fmaxf(v2, v3));
        }
        rmax0 = fmaxf(rmax0, __shfl_xor_sync(0xffffffffu, rmax0, 1));
        rmax0 = fmaxf(rmax0, __shfl_xor_sync(0xffffffffu, rmax0, 2));
        rmax1 = fmaxf(rmax1, __shfl_xor_sync(0xffffffffu, rmax1, 1));
        rmax1 = fmaxf(rmax1, __shfl_xor_sync(0xffffffffu, rmax1, 2));
        const float mn0 = fmaxf(m0, rmax0), mn1 = fmaxf(m1, rmax1);
        const float al0 = __expf(m0 - mn0), al1 = __expf(m1 - mn1);
        m0 = mn0; m1 = mn1;

        float rs0 = 0.f, rs1 = 0.f;
        uint32_t pha[4][4], pla[4][4];
        #pragma unroll
        for (int j = 0; j < 8; j++) {
            const float p0 = __expf(cl[j][0] - mn0);
            const float p1 = __expf(cl[j][1] - mn0);
            const float p2 = __expf(cl[j][2] - mn1);
            const float p3 = __expf(cl[j][3] - mn1);
            rs0 += p0 + p1; rs1 += p2 + p3;
            const int ks = j >> 1, pos = (j & 1) * 2;
            pha[ks][pos]     = pack_split(p0, p1, pla[ks][pos]);
            pha[ks][pos + 1] = pack_split(p2, p3, pla[ks][pos + 1]);
        }
        rs0 += __shfl_xor_sync(0xffffffffu, rs0, 1);
        rs0 += __shfl_xor_sync(0xffffffffu, rs0, 2);
        rs1 += __shfl_xor_sync(0xffffffffu, rs1, 1);
        rs1 += __shfl_xor_sync(0xffffffffu, rs1, 2);
        s0 = s0 * al0 + rs0;
        s1 = s1 * al1 + rs1;

        // rescale O and accumulate P x V (3-pass)
        #pragma unroll
        for (int j = 0; j < 8; j++) {
            acc_o[j][0] *= al0; acc_o[j][1] *= al0;
            acc_o[j][2] *= al1; acc_o[j][3] *= al1;
        }
        {
            const uint32_t vb = base + OFF_V + buf * 2 * F_T;
            #pragma unroll
            for (int ks = 0; ks < 4; ks++) {
                uint32_t bh[4][4], bl[4][4];
                #pragma unroll
                for (int jp = 0; jp < 4; jp++) {
                    const uint32_t off = SWZ128((uint32_t)((16 * jp + b_noff) * 128 + ks * 32 + b_koff));
                    ldsm_x4(bh[jp], vb + off);
                    ldsm_x4(bl[jp], vb + F_T + off);
                }
                #pragma unroll
                for (int j = 0; j < 8; j++)
                    mma16816(acc_o[j], pha[ks], &bh[j >> 1][(j & 1) * 2]);
                #pragma unroll
                for (int j = 0; j < 8; j++)
                    mma16816(acc_o[j], pha[ks], &bl[j >> 1][(j & 1) * 2]);
                #pragma unroll
                for (int j = 0; j < 8; j++)
                    mma16816(acc_o[j], pla[ks], &bh[j >> 1][(j & 1) * 2]);
            }
        }
        __syncthreads();
    }

    // epilogue: normalize and write bf16-split O
    const float inv0 = 1.f / s0, inv1 = 1.f / s1;
    #pragma unroll
    for (int j = 0; j < 8; j++) {
        const int col = h * 64 + 8 * j + c2;
        const size_t o1 = ((size_t)(b * NQ + q0 + row0)) * ND + col;
        const size_t o2 = ((size_t)(b * NQ + q0 + row1)) * ND + col;
        store_split2(&g_OH[o1], &g_OL[o1], acc_o[j][0] * inv0, acc_o[j][1] * inv0);
        store_split2(&g_OH[o2], &g_OL[o2], acc_o[j][2] * inv1, acc_o[j][3] * inv1);
    }
}

// ---------------------------------------------------------------------------
extern "C" void kernel_launch(void* const* d_in, const int* in_sizes, int n_in,
                              void* d_out, int out_size)
{
    const float* qry = (const float*)d_in[0];
    const float* mem = (const float*)d_in[1];
    const float* pe  = (const float*)d_in[2];
    const float* cb  = (const float*)d_in[4];
    const float* pb  = (const float*)d_in[5];
    const float* Wq  = (const float*)d_in[6];
    const float* Wkc = (const float*)d_in[7];
    const float* Wkp = (const float*)d_in[8];
    const float* Wv  = (const float*)d_in[9];
    const float* Wo  = (const float*)d_in[10];
    float* out = (float*)d_out;

    cudaFuncSetAttribute(mma_gemm<MODE_Q>,   cudaFuncAttributeMaxDynamicSharedMemorySize, GSMEM);
    cudaFuncSetAttribute(mma_gemm<MODE_KC>,  cudaFuncAttributeMaxDynamicSharedMemorySize, GSMEM);
    cudaFuncSetAttribute(mma_gemm<MODE_V>,   cudaFuncAttributeMaxDynamicSharedMemorySize, GSMEM);
    cudaFuncSetAttribute(mma_gemm<MODE_KP>,  cudaFuncAttributeMaxDynamicSharedMemorySize, GSMEM);
    cudaFuncSetAttribute(mma_gemm<MODE_OUT>, cudaFuncAttributeMaxDynamicSharedMemorySize, GSMEM);
    cudaFuncSetAttribute(fused_attn, cudaFuncAttributeMaxDynamicSharedMemorySize, FSMEM);

    dim3 thr(256);
    dim3 wtb(32, 8);

    // conversions
    conv_xref<<<NB * NR, 256>>>(qry, mem);
    conv_pe<<<(NR * ND) / 256, 256>>>(pe);
    conv_wt<0><<<dim3(32, 32), wtb>>>(Wq);
    conv_wt<1><<<dim3(32, 32), wtb>>>(Wkc);
    conv_wt<2><<<dim3(32, 32), wtb>>>(Wkp);
    conv_wt<3><<<dim3(32, 32), wtb>>>(Wv);
    conv_wt<4><<<dim3(32, 32), wtb>>>(Wo);

    // projections (split bf16 mma.sync)
    mma_gemm<MODE_Q ><<<dim3(8, 32), thr, GSMEM>>>(cb, pb, nullptr);
    mma_gemm<MODE_KC><<<dim3(8, 64), thr, GSMEM>>>(nullptr, nullptr, nullptr);
    mma_gemm<MODE_V ><<<dim3(8, 64), thr, GSMEM>>>(nullptr, nullptr, nullptr);
    mma_gemm<MODE_KP><<<dim3(8, 8),  thr, GSMEM>>>(nullptr, nullptr, nullptr);

    // fused flash attention (score + rel-shift + softmax + P*V)
    fused_attn<<<dim3(8, NB * NH), 128, FSMEM>>>();

    // output projection
    mma_gemm<MODE_OUT><<<dim3(8, 32), thr, GSMEM>>>(nullptr, nullptr, out);
}

// round 11
// speedup vs baseline: 4.6309x; 1.0266x over previous
#include <cuda_runtime.h>
#include <cuda_bf16.h>
#include <math.h>
#include <stdint.h>

// Problem constants
constexpr int NB = 8;     // batch
constexpr int NQ = 512;   // query len
constexpr int NM = 512;   // memory len
constexpr int NR = 1024;  // reference len
constexpr int NH = 16;    // heads
constexpr int NS = 64;    // size per head
constexpr int ND = 1024;  // hidden

#define ALGN __align__(16)

// bf16 split attention operands (written by projection epilogues)
__device__ ALGN __nv_bfloat16 g_QCh[(size_t)NB*NH*NQ*NS];
__device__ ALGN __nv_bfloat16 g_QCl[(size_t)NB*NH*NQ*NS];
__device__ ALGN __nv_bfloat16 g_QPh[(size_t)NB*NH*NQ*NS];
__device__ ALGN __nv_bfloat16 g_QPl[(size_t)NB*NH*NQ*NS];
__device__ ALGN __nv_bfloat16 g_KCh[(size_t)NB*NH*NR*NS];
__device__ ALGN __nv_bfloat16 g_KCl[(size_t)NB*NH*NR*NS];
__device__ ALGN __nv_bfloat16 g_KPh[(size_t)NH*NR*NS];
__device__ ALGN __nv_bfloat16 g_KPl[(size_t)NH*NR*NS];
__device__ ALGN __nv_bfloat16 g_VtH[(size_t)NB*NH*NS*NR];  // V transposed [z][s][r]
__device__ ALGN __nv_bfloat16 g_VtL[(size_t)NB*NH*NS*NR];
// attention output (bf16 split, written by fused_attn)
__device__ ALGN __nv_bfloat16 g_OH[(size_t)NB*NQ*ND];
__device__ ALGN __nv_bfloat16 g_OL[(size_t)NB*NQ*ND];

// bf16 split inputs for projections
__device__ ALGN __nv_bfloat16 g_XrefH[(size_t)NB*NR*ND];
__device__ ALGN __nv_bfloat16 g_XrefL[(size_t)NB*NR*ND];
__device__ ALGN __nv_bfloat16 g_PEH[(size_t)NR*ND];
__device__ ALGN __nv_bfloat16 g_PEL[(size_t)NR*ND];
// transposed weights Wt[c][k]: 0=Wq 1=Wkc 2=Wkp 3=Wv 4=Wo
__device__ ALGN __nv_bfloat16 g_WtH[5][(size_t)ND*ND];
__device__ ALGN __nv_bfloat16 g_WtL[5][(size_t)ND*ND];

enum { MODE_Q = 0, MODE_KC = 1, MODE_V = 2, MODE_KP = 3, MODE_OUT = 4 };

// ---------------------------------------------------------------------------
// helpers
// ---------------------------------------------------------------------------
__device__ __forceinline__ uint32_t smem_u32(const void* p) {
    uint32_t a;
    asm("{ .reg .u64 t; cvta.to.shared.u64 t, %1; cvt.u32.u64 %0, t; }"
        : "=r"(a) : "l"(p));
    return a;
}
__device__ __forceinline__ void cp16(uint32_t dst, const void* src) {
    asm volatile("cp.async.cg.shared.global [%0], [%1], 16;"
                 :: "r"(dst), "l"(src) : "memory");
}
__device__ __forceinline__ void ldsm_x4(uint32_t* r, uint32_t addr) {
    asm volatile("ldmatrix.sync.aligned.m8n8.x4.shared.b16 {%0,%1,%2,%3}, [%4];"
                 : "=r"(r[0]), "=r"(r[1]), "=r"(r[2]), "=r"(r[3]) : "r"(addr));
}
__device__ __forceinline__ void mma16816(float* c, const uint32_t* a, const uint32_t* b) {
    asm volatile(
        "mma.sync.aligned.m16n8k16.row.col.f32.bf16.bf16.f32 "
        "{%0,%1,%2,%3}, {%4,%5,%6,%7}, {%8,%9}, {%0,%1,%2,%3};"
        : "+f"(c[0]), "+f"(c[1]), "+f"(c[2]), "+f"(c[3])
        : "r"(a[0]), "r"(a[1]), "r"(a[2]), "r"(a[3]), "r"(b[0]), "r"(b[1]));
}
#define SWZ64(x)  ((x) ^ (((x) >> 3) & 0x30))
#define SWZ128(x) ((x) ^ (((x) >> 3) & 0x70))

__device__ __forceinline__ void split1(float v, __nv_bfloat16& h, __nv_bfloat16& l) {
    h = __float2bfloat16(v);
    l = __float2bfloat16(v - __bfloat162float(h));
}
__device__ __forceinline__ void store_split2(__nv_bfloat16* ph, __nv_bfloat16* pl,
                                             float a, float b) {
    __nv_bfloat162 hh, ll;
    hh.x = __float2bfloat16(a);
    ll.x = __float2bfloat16(a - __bfloat162float(hh.x));
    hh.y = __float2bfloat16(b);
    ll.y = __float2bfloat16(b - __bfloat162float(hh.y));
    *(__nv_bfloat162*)ph = hh;
    *(__nv_bfloat162*)pl = ll;
}
__device__ __forceinline__ uint32_t pack_split(float a, float b, uint32_t& lo) {
    __nv_bfloat162 hh, ll;
    hh.x = __float2bfloat16(a);
    ll.x = __float2bfloat16(a - __bfloat162float(hh.x));
    hh.y = __float2bfloat16(b);
    ll.y = __float2bfloat16(b - __bfloat162float(hh.y));
    lo = *(uint32_t*)&ll;
    return *(uint32_t*)&hh;
}

// ---------------------------------------------------------------------------
// Conversion kernels
// ---------------------------------------------------------------------------
__global__ void conv_xref(const float* __restrict__ qry, const float* __restrict__ mem) {
    const int row = blockIdx.x;
    const int b = row >> 10, r = row & 1023;
    const float* src = (r < NM) ? mem + ((size_t)(b * NM + r)) * ND
                                : qry + ((size_t)(b * NQ + (r - NM))) * ND;
    const int c = threadIdx.x * 4;
    float4 v = *(const float4*)(src + c);
    const size_t o = (size_t)row * ND + c;
    split1(v.x, g_XrefH[o+0], g_XrefL[o+0]);
    split1(v.y, g_XrefH[o+1], g_XrefL[o+1]);
    split1(v.z, g_XrefH[o+2], g_XrefL[o+2]);
    split1(v.w, g_XrefH[o+3], g_XrefL[o+3]);
}

__global__ void conv_pe(const float* __restrict__ src) {
    const size_t i = (size_t)blockIdx.x * blockDim.x + threadIdx.x;
    split1(src[i], g_PEH[i], g_PEL[i]);
}

template <int WID>
__global__ void conv_wt(const float* __restrict__ W) {
    __shared__ float tile[32][33];
    const int c0 = blockIdx.x * 32, k0 = blockIdx.y * 32;
    const int tx = threadIdx.x, ty = threadIdx.y;  // 32 x 8
    for (int i = ty; i < 32; i += 8)
        tile[i][tx] = W[(size_t)(k0 + i) * ND + c0 + tx];
    __syncthreads();
    for (int i = ty; i < 32; i += 8) {
        float v = tile[tx][i];
        __nv_bfloat16 h, l;
        split1(v, h, l);
        const size_t o = (size_t)(c0 + i) * ND + k0 + tx;
        g_WtH[WID][o] = h;
        g_WtL[WID][o] = l;
    }
}

// ---------------------------------------------------------------------------
// Split-bf16 mma.sync projection GEMM (3-pass) — unchanged (passing R9).
// ---------------------------------------------------------------------------
constexpr int TILEB  = 128 * 64;
constexpr int STAGEB = 4 * TILEB;
constexpr int GSMEM  = 2 * STAGEB + 1024;
constexpr int NCHUNK = ND / 32;

template <int MODE>
__global__ __launch_bounds__(256)
void mma_gemm(const float* __restrict__ cb, const float* __restrict__ pb,
              float* __restrict__ outp)
{
    extern __shared__ char dsm[];
    const uint32_t dyn_u32 = smem_u32(dsm);
    const uint32_t base = (dyn_u32 + 1023u) & ~1023u;
    float* stg = reinterpret_cast<float*>(dsm + (base - dyn_u32));

    const int t = threadIdx.x;
    const int wid = t >> 5, lane = t & 31;
    const int n0 = blockIdx.x * 128;
    const int m0 = blockIdx.y * 128;
    const int arow0 = (MODE == MODE_Q) ? ((m0 >> 9) * 1024 + 512 + (m0 & 511)) : m0;

    const __nv_bfloat16 *Ah, *Al, *Bh, *Bl;
    if (MODE == MODE_Q)       { Ah = g_XrefH; Al = g_XrefL; Bh = g_WtH[0]; Bl = g_WtL[0]; }
    else if (MODE == MODE_KC) { Ah = g_XrefH; Al = g_XrefL; Bh = g_WtH[1]; Bl = g_WtL[1]; }
    else if (MODE == MODE_KP) { Ah = g_PEH;   Al = g_PEL;   Bh = g_WtH[2]; Bl = g_WtL[2]; }
    else if (MODE == MODE_V)  { Ah = g_XrefH; Al = g_XrefL; Bh = g_WtH[3]; Bl = g_WtL[3]; }
    else                      { Ah = g_OH;    Al = g_OL;    Bh = g_WtH[4]; Bl = g_WtL[4]; }

    const int s0 = t;
    const int mseg0 = s0 >> 2, cseg0 = s0 & 3;
    const int s1 = t + 256;
    const int mseg1 = s1 >> 2, cseg1 = s1 & 3;

    auto load_stage = [&](int chunk, int buf) {
        const uint32_t sb = base + buf * STAGEB;
        const int kbyte = chunk * 64;
        {
            const char* a0 = (const char*)(Ah + (size_t)(arow0 + mseg0) * ND) + kbyte + cseg0 * 16;
            const char* a1 = (const char*)(Al + (size_t)(arow0 + mseg0) * ND) + kbyte + cseg0 * 16;
            const char* b0 = (const char*)(Bh + (size_t)(n0 + mseg0) * ND) + kbyte + cseg0 * 16;
            const char* b1 = (const char*)(Bl + (size_t)(n0 + mseg0) * ND) + kbyte + cseg0 * 16;
            const uint32_t sw = SWZ64((uint32_t)(mseg0 * 64 + cseg0 * 16));
            cp16(sb + 0 * TILEB + sw, a0);
            cp16(sb + 1 * TILEB + sw, a1);
            cp16(sb + 2 * TILEB + sw, b0);
            cp16(sb + 3 * TILEB + sw, b1);
        }
        {
            const char* a0 = (const char*)(Ah + (size_t)(arow0 + mseg1) * ND) + kbyte + cseg1 * 16;
            const char* a1 = (const char*)(Al + (size_t)(arow0 + mseg1) * ND) + kbyte + cseg1 * 16;
            const char* b0 = (const char*)(Bh + (size_t)(n0 + mseg1) * ND) + kbyte + cseg1 * 16;
            const char* b1 = (const char*)(Bl + (size_t)(n0 + mseg1) * ND) + kbyte + cseg1 * 16;
            const uint32_t sw = SWZ64((uint32_t)(mseg1 * 64 + cseg1 * 16));
            cp16(sb + 0 * TILEB + sw, a0);
            cp16(sb + 1 * TILEB + sw, a1);
            cp16(sb + 2 * TILEB + sw, b0);
            cp16(sb + 3 * TILEB + sw, b1);
        }
        asm volatile("cp.async.commit_group;" ::: "memory");
    };

    const int wm = wid >> 1;
    const int wn = wid & 1;
    const int mbase = wm * 32;
    const int nbase = wn * 64;

    const int tle = lane >> 3;
    const int rin = lane & 7;
    const int a_moff = rin + (tle & 1) * 8;
    const int a_koff = (tle >> 1) * 16;
    const int b_noff = (tle < 2) ? rin : (rin + 8);
    const int b_koff = (tle & 1) * 16;

    float acc[2][8][4];
    #pragma unroll
    for (int i = 0; i < 2; i++)
        #pragma unroll
        for (int j = 0; j < 8; j++)
            #pragma unroll
            for (int k = 0; k < 4; k++) acc[i][j][k] = 0.f;

    auto compute_stage = [&](int buf) {
        const uint32_t sb = base + buf * STAGEB;
        #pragma unroll
        for (int ks = 0; ks < 2; ks++) {
            uint32_t ah[2][4], al[2][4], bh[4][4], bl[4][4];
            #pragma unroll
            for (int i = 0; i < 2; i++) {
                const uint32_t off = SWZ64((uint32_t)((mbase + 16 * i + a_moff) * 64 + ks * 32 + a_koff));
                ldsm_x4(ah[i], sb + 0 * TILEB + off);
                ldsm_x4(al[i], sb + 1 * TILEB + off);
            }
            #pragma unroll
            for (int jp = 0; jp < 4; jp++) {
                const uint32_t off = SWZ64((uint32_t)((nbase + 16 * jp + b_noff) * 64 + ks * 32 + b_koff));
                ldsm_x4(bh[jp], sb + 2 * TILEB + off);
                ldsm_x4(bl[jp], sb + 3 * TILEB + off);
            }
            #pragma unroll
            for (int i = 0; i < 2; i++) {
                #pragma unroll
                for (int j = 0; j < 8; j++)
                    mma16816(acc[i][j], ah[i], &bh[j >> 1][(j & 1) * 2]);
                #pragma unroll
                for (int j = 0; j < 8; j++)
                    mma16816(acc[i][j], ah[i], &bl[j >> 1][(j & 1) * 2]);
                #pragma unroll
                for (int j = 0; j < 8; j++)
                    mma16816(acc[i][j], al[i], &bh[j >> 1][(j & 1) * 2]);
            }
        }
    };

    load_stage(0, 0);
    for (int c = 0; c < NCHUNK; c++) {
        const int buf = c & 1;
        if (c + 1 < NCHUNK) {
            load_stage(c + 1, buf ^ 1);
            asm volatile("cp.async.wait_group 1;" ::: "memory");
        } else {
            asm volatile("cp.async.wait_group 0;" ::: "memory");
        }
        __syncthreads();
        compute_stage(buf);
        __syncthreads();
    }

    const int lr = lane >> 2;
    const int lc = (lane & 3) * 2;
    for (int p = 0; p < 2; p++) {
        if ((wm >> 1) == p) {
            const int rb = mbase - p * 64;
            #pragma unroll
            for (int i = 0; i < 2; i++) {
                #pragma unroll
                for (int j = 0; j < 8; j++) {
                    const int rr = rb + 16 * i + lr;
                    const int cc = nbase + 8 * j + lc;
                    *(float2*)&stg[rr * 132 + cc]       = make_float2(acc[i][j][0], acc[i][j][1]);
                    *(float2*)&stg[(rr + 8) * 132 + cc] = make_float2(acc[i][j][2], acc[i][j][3]);
                }
            }
        }
        __syncthreads();
        if (MODE == MODE_V) {
            const int c = t >> 1;
            const int rseg = (t & 1) * 32;
            const int b = m0 >> 10;
            const int h = (n0 + c) >> 6, sO = (n0 + c) & 63;
            const int rglob0 = (m0 & 1023) + 64 * p + rseg;
            const size_t vo = (((size_t)(b * NH + h)) * NS + sO) * NR + rglob0;
            #pragma unroll 8
            for (int rl = 0; rl < 32; rl += 2) {
                store_split2(&g_VtH[vo + rl], &g_VtL[vo + rl],
                             stg[(rseg + rl) * 132 + c], stg[(rseg + rl + 1) * 132 + c]);
            }
        } else {
            const int rl = t >> 2;
            const int quad = t & 3;
            const int grow = m0 + 64 * p + rl;
            const int cq = quad * 32;
            const float* sp = stg + rl * 132 + cq;
            if (MODE == MODE_Q) {
                const int b = grow >> 9, q = grow & 511;
                const int h = (n0 + cq) >> 6, sO = (n0 + cq) & 63;
                const size_t o = (((size_t)(b * NH + h)) * NQ + q) * NS + sO;
                const float* cbp = cb + n0 + cq;
                const float* pbp = pb + n0 + cq;
                #pragma unroll
                for (int j = 0; j < 32; j += 2) {
                    const float v0 = sp[j], v1 = sp[j + 1];
                    store_split2(&g_QCh[o + j], &g_QCl[o + j], v0 + cbp[j], v1 + cbp[j + 1]);
                    store_split2(&g_QPh[o + j], &g_QPl[o + j], v0 + pbp[j], v1 + pbp[j + 1]);
                }
            } else if (MODE == MODE_KC) {
                const int b = grow >> 10, r = grow & 1023;
                const int h = (n0 + cq) >> 6, sO = (n0 + cq) & 63;
                const size_t o = (((size_t)(b * NH + h)) * NR + r) * NS + sO;
                #pragma unroll
                for (int j = 0; j < 32; j += 2)
                    store_split2(&g_KCh[o + j], &g_KCl[o + j], sp[j], sp[j + 1]);
            } else if (MODE == MODE_KP) {
                const int h = (n0 + cq) >> 6, sO = (n0 + cq) & 63;
                const size_t o = ((size_t)h * NR + grow) * NS + sO;
                #pragma unroll
                for (int j = 0; j < 32; j += 2)
                    store_split2(&g_KPh[o + j], &g_KPl[o + j], sp[j], sp[j + 1]);
            } else {
                float* d1 = outp + (size_t)grow * ND + n0 + cq;
                #pragma unroll
                for (int j = 0; j < 32; j += 4)
                    *(float4*)(d1 + j) = make_float4(sp[j], sp[j+1], sp[j+2], sp[j+3]);
            }
        }
        __syncthreads();
    }
}

// ---------------------------------------------------------------------------
// fused_attn: fused score + rel-shift + online softmax + P*V with a ROLLING
// positional band: each PP tile is computed exactly once (2-bank parity cache)
// instead of twice. KP ring shrinks to 2 slots. 288 mma/warp/iter (was 384).
// ---------------------------------------------------------------------------
constexpr int F_T    = 8192;           // one 64x128B tile
constexpr int OFF_Q  = 0;              // QCh,QCl,QPh,QPl
constexpr int OFF_KC = 4 * F_T;        // 2 bufs x (h,l)
constexpr int OFF_V  = 8 * F_T;        // 2 bufs x (h,l)
constexpr int OFF_KP = 12 * F_T;       // 2 slots x (h,l)
constexpr int OFF_PP = 16 * F_T;       // 2 banks x 64 x 66 fp32
constexpr int PPS    = 66;
constexpr int PPBANK = 64 * PPS;       // floats per bank
constexpr int FSMEM  = OFF_PP + 2 * PPBANK * 4 + 1024;

__global__ __launch_bounds__(128)
void fused_attn()
{
    extern __shared__ char fsm[];
    const uint32_t raw = smem_u32(fsm);
    const uint32_t base = (raw + 1023u) & ~1023u;
    float* sPP = reinterpret_cast<float*>(fsm + (base - raw) + OFF_PP);

    const int qt = blockIdx.x;
    const int z  = blockIdx.y;
    const int q0 = qt * 64;
    const int b = z >> 4, h = z & 15;
    const int nt = qt + 9;
    const int tj0 = 7 - qt;

    const int t = threadIdx.x;
    const int wid = t >> 5, lane = t & 31;
    const int mrow = wid * 16;

    const char* QCh = (const char*)(g_QCh + ((size_t)z * NQ + q0) * NS);
    const char* QCl = (const char*)(g_QCl + ((size_t)z * NQ + q0) * NS);
    const char* QPh = (const char*)(g_QPh + ((size_t)z * NQ + q0) * NS);
    const char* QPl = (const char*)(g_QPl + ((size_t)z * NQ + q0) * NS);
    const char* KCh = (const char*)(g_KCh + (size_t)z * NR * NS);
    const char* KCl = (const char*)(g_KCl + (size_t)z * NR * NS);
    const char* KPh = (const char*)(g_KPh + (size_t)h * NR * NS);
    const char* KPl = (const char*)(g_KPl + (size_t)h * NR * NS);
    const char* Vh  = (const char*)(g_VtH + (size_t)z * NS * NR);
    const char* Vl  = (const char*)(g_VtL + (size_t)z * NS * NR);

    auto load_kcv = [&](int c, int buf) {
        const uint32_t kb = base + OFF_KC + buf * 2 * F_T;
        const uint32_t vb = base + OFF_V  + buf * 2 * F_T;
        #pragma unroll
        for (int i = 0; i < 4; i++) {
            const int idx = t + 128 * i;
            const int row = idx >> 3, c16 = idx & 7;
            const uint32_t sw = SWZ128((uint32_t)(row * 128 + c16 * 16));
            const size_t kco = (size_t)(c * 64 + row) * 128 + c16 * 16;
            cp16(kb + sw,        KCh + kco);
            cp16(kb + F_T + sw,  KCl + kco);
            const size_t vo = (size_t)row * (NR * 2) + (size_t)c * 128 + c16 * 16;
            cp16(vb + sw,        Vh + vo);
            cp16(vb + F_T + sw,  Vl + vo);
        }
    };
    auto load_kp = [&](int tj) {
        const int slot = tj & 1;
        const uint32_t kb = base + OFF_KP + slot * 2 * F_T;
        #pragma unroll
        for (int i = 0; i < 4; i++) {
            const int idx = t + 128 * i;
            const int row = idx >> 3, c16 = idx & 7;
            int k = tj * 64 + row;
            if (k > 1023) k = 1023;               // clamped rows are masked later
            const uint32_t sw = SWZ128((uint32_t)(row * 128 + c16 * 16));
            cp16(kb + sw,       KPh + (size_t)k * 128 + c16 * 16);
            cp16(kb + F_T + sw, KPl + (size_t)k * 128 + c16 * 16);
        }
    };

    // prologue loads: Q tiles + first KC/V + KP tiles tj0, tj0+1
    #pragma unroll
    for (int i = 0; i < 4; i++) {
        const int idx = t + 128 * i;
        const int row = idx >> 3, c16 = idx & 7;
        const uint32_t sw = SWZ128((uint32_t)(row * 128 + c16 * 16));
        const size_t qo = (size_t)row * 128 + c16 * 16;
        cp16(base + OFF_Q + 0 * F_T + sw, QCh + qo);
        cp16(base + OFF_Q + 1 * F_T + sw, QCl + qo);
        cp16(base + OFF_Q + 2 * F_T + sw, QPh + qo);
        cp16(base + OFF_Q + 3 * F_T + sw, QPl + qo);
    }
    load_kcv(0, 0);
    load_kp(tj0);
    load_kp(tj0 + 1);
    asm volatile("cp.async.commit_group;" ::: "memory");
    asm volatile("cp.async.wait_group 0;" ::: "memory");
    __syncthreads();

    const int tle = lane >> 3;
    const int rin = lane & 7;
    const int a_moff = rin + (tle & 1) * 8;
    const int a_koff = (tle >> 1) * 16;
    const int b_noff = (tle < 2) ? rin : (rin + 8);
    const int b_koff = (tle & 1) * 16;
    const int r_ = lane >> 2;
    const int c2 = (lane & 3) * 2;
    const int row0 = mrow + r_;
    const int row1 = row0 + 8;

    // preload Q a-frags (persistent)
    uint32_t qch[4][4], qcl[4][4], qph[4][4], qpl[4][4];
    #pragma unroll
    for (int ks = 0; ks < 4; ks++) {
        const uint32_t off = SWZ128((uint32_t)((mrow + a_moff) * 128 + ks * 32 + a_koff));
        ldsm_x4(qch[ks], base + OFF_Q + 0 * F_T + off);
        ldsm_x4(qcl[ks], base + OFF_Q + 1 * F_T + off);
        ldsm_x4(qph[ks], base + OFF_Q + 2 * F_T + off);
        ldsm_x4(qpl[ks], base + OFF_Q + 3 * F_T + off);
    }

    // compute one PP tile (3-pass) from KP slot tj&1 into PP bank tj&1
    auto pp_tile = [&](int tj) {
        const uint32_t kb = base + OFF_KP + (tj & 1) * 2 * F_T;
        float pa[8][4];
        #pragma unroll
        for (int j = 0; j < 8; j++)
            #pragma unroll
            for (int e = 0; e < 4; e++) pa[j][e] = 0.f;
        #pragma unroll
        for (int ks = 0; ks < 4; ks++) {
            uint32_t bh[4][4], bl[4][4];
            #pragma unroll
            for (int jp = 0; jp < 4; jp++) {
                const uint32_t off = SWZ128((uint32_t)((16 * jp + b_noff) * 128 + ks * 32 + b_koff));
                ldsm_x4(bh[jp], kb + off);
                ldsm_x4(bl[jp], kb + F_T + off);
            }
            #pragma unroll
            for (int j = 0; j < 8; j++)
                mma16816(pa[j], qph[ks], &bh[j >> 1][(j & 1) * 2]);
            #pragma unroll
            for (int j = 0; j < 8; j++)
                mma16816(pa[j], qph[ks], &bl[j >> 1][(j & 1) * 2]);
            #pragma unroll
            for (int j = 0; j < 8; j++)
                mma16816(pa[j], qpl[ks], &bh[j >> 1][(j & 1) * 2]);
        }
        float* bw = sPP + (tj & 1) * PPBANK;
        #pragma unroll
        for (int j = 0; j < 8; j++) {
            const int col = 8 * j + c2;
            *(float2*)&bw[row0 * PPS + col] = make_float2(pa[j][0], pa[j][1]);
            *(float2*)&bw[row1 * PPS + col] = make_float2(pa[j][2], pa[j][3]);
        }
    };

    // prologue PP: tile T(0) = tj0
    pp_tile(tj0);
    __syncthreads();   // all warps done reading KP slot tj0&1 before iter-0 prefetch reuses it

    float m0 = -1e30f, m1 = -1e30f, s0 = 0.f, s1 = 0.f;
    float acc_o[8][4];
    #pragma unroll
    for (int j = 0; j < 8; j++)
        #pragma unroll
        for (int e = 0; e < 4; e++) acc_o[j][e] = 0.f;

    for (int c = 0; c < nt; c++) {
        const int buf = c & 1;
        if (c + 1 < nt) {
            load_kcv(c + 1, buf ^ 1);
            load_kp(tj0 + c + 2);
            asm volatile("cp.async.commit_group;" ::: "memory");
            asm volatile("cp.async.wait_group 1;" ::: "memory");
        } else {
            asm volatile("cp.async.wait_group 0;" ::: "memory");
        }
        __syncthreads();

        // --- new positional tile T(c+1) (single tile per iteration) ---
        pp_tile(tj0 + c + 1);

        // --- content logits (3-pass, K=64) ---
        float cl[8][4];
        #pragma unroll
        for (int j = 0; j < 8; j++)
            #pragma unroll
            for (int e = 0; e < 4; e++) cl[j][e] = 0.f;
        {
            const uint32_t kb = base + OFF_KC + buf * 2 * F_T;
            #pragma unroll
            for (int ks = 0; ks < 4; ks++) {
                uint32_t bh[4][4], bl[4][4];
                #pragma unroll
                for (int jp = 0; jp < 4; jp++) {
                    const uint32_t off = SWZ128((uint32_t)((16 * jp + b_noff) * 128 + ks * 32 + b_koff));
                    ldsm_x4(bh[jp], kb + off);
                    ldsm_x4(bl[jp], kb + F_T + off);
                }
                #pragma unroll
                for (int j = 0; j < 8; j++)
                    mma16816(cl[j], qch[ks], &bh[j >> 1][(j & 1) * 2]);
                #pragma unroll
                for (int j = 0; j < 8; j++)
                    mma16816(cl[j], qch[ks], &bl[j >> 1][(j & 1) * 2]);
                #pragma unroll
                for (int j = 0; j < 8; j++)
                    mma16816(cl[j], qcl[ks], &bh[j >> 1][(j & 1) * 2]);
            }
        }
        __syncthreads();   // PP tile visible before gather

        // --- gather (2-bank rolling window) + mask + online softmax ---
        const int lowpar = (tj0 + c) & 1;
        const float* bL = sPP + lowpar * PPBANK;
        const float* bH = sPP + (lowpar ^ 1) * PPBANK;
        const bool last = (c == nt - 1);
        float rmax0 = -1e30f, rmax1 = -1e30f;
        #pragma unroll
        for (int j = 0; j < 8; j++) {
            const int rj = 8 * j + c2;
            const int o0a = rj + 63 - row0, o0b = o0a + 1;
            const int o1a = rj + 63 - row1, o1b = o1a + 1;
            float v0 = (cl[j][0] + (o0a < 64 ? bL[row0 * PPS + o0a] : bH[row0 * PPS + o0a - 64])) * 0.125f;
            float v1 = (cl[j][1] + (o0b < 64 ? bL[row0 * PPS + o0b] : bH[row0 * PPS + o0b - 64])) * 0.125f;
            float v2 = (cl[j][2] + (o1a < 64 ? bL[row1 * PPS + o1a] : bH[row1 * PPS + o1a - 64])) * 0.125f;
            float v3 = (cl[j][3] + (o1b < 64 ? bL[row1 * PPS + o1b] : bH[row1 * PPS + o1b - 64])) * 0.125f;
            if (last) {
                if (rj     > row0) v0 = -1e30f;
                if (rj + 1 > row0) v1 = -1e30f;
                if (rj     > row1) v2 = -1e30f;
                if (rj + 1 > row1) v3 = -1e30f;
            }
            cl[j][0] = v0; cl[j][1] = v1; cl[j][2] = v2; cl[j][3] = v3;
            rmax0 = fmaxf(rmax0, fmaxf(v0, v1));
            rmax1 = fmaxf(rmax1, fmaxf(v2, v3));
        }
        rmax0 = fmaxf(rmax0, __shfl_xor_sync(0xffffffffu, rmax0, 1));
        rmax0 = fmaxf(rmax0, __shfl_xor_sync(0xffffffffu, rmax0, 2));
        rmax1 = fmaxf(rmax1, __shfl_xor_sync(0xffffffffu, rmax1, 1));
        rmax1 = fmaxf(rmax1, __shfl_xor_sync(0xffffffffu, rmax1, 2));
        const float mn0 = fmaxf(m0, rmax0), mn1 = fmaxf(m1, rmax1);
        const float al0 = __expf(m0 - mn0), al1 = __expf(m1 - mn1);
        m0 = mn0; m1 = mn1;

        float rs0 = 0.f, rs1 = 0.f;
        uint32_t pha[4][4], pla[4][4];
        #pragma unroll
        for (int j = 0; j < 8; j++) {
            const float p0 = __expf(cl[j][0] - mn0);
            const float p1 = __expf(cl[j][1] - mn0);
            const float p2 = __expf(cl[j][2] - mn1);
            const float p3 = __expf(cl[j][3] - mn1);
            rs0 += p0 + p1; rs1 += p2 + p3;
            const int ks = j >> 1, pos = (j & 1) * 2;
            pha[ks][pos]     = pack_split(p0, p1, pla[ks][pos]);
            pha[ks][pos + 1] = pack_split(p2, p3, pla[ks][pos + 1]);
        }
        rs0 += __shfl_xor_sync(0xffffffffu, rs0, 1);
        rs0 += __shfl_xor_sync(0xffffffffu, rs0, 2);
        rs1 += __shfl_xor_sync(0xffffffffu, rs1, 1);
        rs1 += __shfl_xor_sync(0xffffffffu, rs1, 2);
        s0 = s0 * al0 + rs0;
        s1 = s1 * al1 + rs1;

        // rescale O and accumulate P x V (3-pass)
        #pragma unroll
        for (int j = 0; j < 8; j++) {
            acc_o[j][0] *= al0; acc_o[j][1] *= al0;
            acc_o[j][2] *= al1; acc_o[j][3] *= al1;
        }
        {
            const uint32_t vb = base + OFF_V + buf * 2 * F_T;
            #pragma unroll
            for (int ks = 0; ks < 4; ks++) {
                uint32_t bh[4][4], bl[4][4];
                #pragma unroll
                for (int jp = 0; jp < 4; jp++) {
                    const uint32_t off = SWZ128((uint32_t)((16 * jp + b_noff) * 128 + ks * 32 + b_koff));
                    ldsm_x4(bh[jp], vb + off);
                    ldsm_x4(bl[jp], vb + F_T + off);
                }
                #pragma unroll
                for (int j = 0; j < 8; j++)
                    mma16816(acc_o[j], pha[ks], &bh[j >> 1][(j & 1) * 2]);
                #pragma unroll
                for (int j = 0; j < 8; j++)
                    mma16816(acc_o[j], pha[ks], &bl[j >> 1][(j & 1) * 2]);
                #pragma unroll
                for (int j = 0; j < 8; j++)
                    mma16816(acc_o[j], pla[ks], &bh[j >> 1][(j & 1) * 2]);
            }
        }
        __syncthreads();
    }

    // epilogue: normalize and write bf16-split O
    const float inv0 = 1.f / s0, inv1 = 1.f / s1;
    #pragma unroll
    for (int j = 0; j < 8; j++) {
        const int col = h * 64 + 8 * j + c2;
        const size_t o1 = ((size_t)(b * NQ + q0 + row0)) * ND + col;
        const size_t o2 = ((size_t)(b * NQ + q0 + row1)) * ND + col;
        store_split2(&g_OH[o1], &g_OL[o1], acc_o[j][0] * inv0, acc_o[j][1] * inv0);
        store_split2(&g_OH[o2], &g_OL[o2], acc_o[j][2] * inv1, acc_o[j][3] * inv1);
    }
}

// ---------------------------------------------------------------------------
extern "C" void kernel_launch(void* const* d_in, const int* in_sizes, int n_in,
                              void* d_out, int out_size)
{
    const float* qry = (const float*)d_in[0];
    const float* mem = (const float*)d_in[1];
    const float* pe  = (const float*)d_in[2];
    const float* cb  = (const float*)d_in[4];
    const float* pb  = (const float*)d_in[5];
    const float* Wq  = (const float*)d_in[6];
    const float* Wkc = (const float*)d_in[7];
    const float* Wkp = (const float*)d_in[8];
    const float* Wv  = (const float*)d_in[9];
    const float* Wo  = (const float*)d_in[10];
    float* out = (float*)d_out;

    cudaFuncSetAttribute(mma_gemm<MODE_Q>,   cudaFuncAttributeMaxDynamicSharedMemorySize, GSMEM);
    cudaFuncSetAttribute(mma_gemm<MODE_KC>,  cudaFuncAttributeMaxDynamicSharedMemorySize, GSMEM);
    cudaFuncSetAttribute(mma_gemm<MODE_V>,   cudaFuncAttributeMaxDynamicSharedMemorySize, GSMEM);
    cudaFuncSetAttribute(mma_gemm<MODE_KP>,  cudaFuncAttributeMaxDynamicSharedMemorySize, GSMEM);
    cudaFuncSetAttribute(mma_gemm<MODE_OUT>, cudaFuncAttributeMaxDynamicSharedMemorySize, GSMEM);
    cudaFuncSetAttribute(fused_attn, cudaFuncAttributeMaxDynamicSharedMemorySize, FSMEM);

    dim3 thr(256);
    dim3 wtb(32, 8);

    // conversions
    conv_xref<<<NB * NR, 256>>>(qry, mem);
    conv_pe<<<(NR * ND) / 256, 256>>>(pe);
    conv_wt<0><<<dim3(32, 32), wtb>>>(Wq);
    conv_wt<1><<<dim3(32, 32), wtb>>>(Wkc);
    conv_wt<2><<<dim3(32, 32), wtb>>>(Wkp);
    conv_wt<3><<<dim3(32, 32), wtb>>>(Wv);
    conv_wt<4><<<dim3(32, 32), wtb>>>(Wo);

    // projections (split bf16 mma.sync)
    mma_gemm<MODE_Q ><<<dim3(8, 32), thr, GSMEM>>>(cb, pb, nullptr);
    mma_gemm<MODE_KC><<<dim3(8, 64), thr, GSMEM>>>(nullptr, nullptr, nullptr);
    mma_gemm<MODE_V ><<<dim3(8, 64), thr, GSMEM>>>(nullptr, nullptr, nullptr);
    mma_gemm<MODE_KP><<<dim3(8, 8),  thr, GSMEM>>>(nullptr, nullptr, nullptr);

    // fused flash attention (score + rel-shift + softmax + P*V, rolling PP)
    fused_attn<<<dim3(8, NB * NH), 128, FSMEM>>>();

    // output projection
    mma_gemm<MODE_OUT><<<dim3(8, 32), thr, GSMEM>>>(nullptr, nullptr, out);
}